// round 2
// baseline (speedup 1.0000x reference)
#include <cuda_runtime.h>
#include <cstdint>

#define BATCH 32
#define MESH  1024
#define EDIM  64
#define DDIM  128
#define TM    64
#define TN    64

#define SE  68   // smem row stride for E tiles and S tile (bank-conflict-free frags)
#define SX  136  // smem row stride for Xs tile
#define STT 132  // smem row stride for T and W tiles

__device__ float g_dinv[BATCH * MESH];
__device__ float g_H1[(size_t)BATCH * MESH * DDIM];

__device__ __forceinline__ float f2tf(float x) {
    uint32_t u;
    asm("cvt.rna.tf32.f32 %0, %1;" : "=r"(u) : "f"(x));
    return __uint_as_float(u);
}
__device__ __forceinline__ uint32_t fb(float x) { return __float_as_uint(x); }

// D(16x8,f32) += A(16x8,tf32,row) * B(8x8,tf32,col)
__device__ __forceinline__ void mma8(float* c, const uint32_t a[4], const uint32_t b[2]) {
    asm volatile(
        "mma.sync.aligned.m16n8k8.row.col.f32.tf32.tf32.f32 "
        "{%0,%1,%2,%3}, {%4,%5,%6,%7}, {%8,%9}, {%0,%1,%2,%3};"
        : "+f"(c[0]), "+f"(c[1]), "+f"(c[2]), "+f"(c[3])
        : "r"(a[0]), "r"(a[1]), "r"(a[2]), "r"(a[3]), "r"(b[0]), "r"(b[1]));
}

// ---------------------------------------------------------------------------
// Pass 1: dinv[b,m] = rsqrt(1 + sum_n relu(e_m . e_n))
// ---------------------------------------------------------------------------
__global__ __launch_bounds__(128) void k_dinv(const float* __restrict__ emb) {
    __shared__ float Em[TM * SE];
    __shared__ float En[TN * SE];
    const int b = blockIdx.y, m0 = blockIdx.x * TM;
    const int tid = threadIdx.x, w = tid >> 5, lane = tid & 31, g = lane >> 2, t = lane & 3;
    const float* Eb = emb + (size_t)b * MESH * EDIM;

    for (int i = tid; i < TM * EDIM / 4; i += 128) {
        int r = i >> 4, c = (i & 15) << 2;
        float4 v = *reinterpret_cast<const float4*>(Eb + (m0 + r) * EDIM + c);
        *reinterpret_cast<float4*>(&Em[r * SE + c]) =
            make_float4(f2tf(v.x), f2tf(v.y), f2tf(v.z), f2tf(v.w));
    }

    float rs0 = 0.f, rs1 = 0.f;
    const int ar = (w * 16 + g) * SE;

    for (int n0 = 0; n0 < MESH; n0 += TN) {
        for (int i = tid; i < TN * EDIM / 4; i += 128) {
            int r = i >> 4, c = (i & 15) << 2;
            float4 v = *reinterpret_cast<const float4*>(Eb + (n0 + r) * EDIM + c);
            *reinterpret_cast<float4*>(&En[r * SE + c]) =
                make_float4(f2tf(v.x), f2tf(v.y), f2tf(v.z), f2tf(v.w));
        }
        __syncthreads();

        float sc[8][4];
#pragma unroll
        for (int j = 0; j < 8; j++) { sc[j][0] = sc[j][1] = sc[j][2] = sc[j][3] = 0.f; }
#pragma unroll
        for (int k = 0; k < 8; k++) {
            const int kc = k * 8 + t;
            uint32_t a[4] = { fb(Em[ar + kc]), fb(Em[ar + 8 * SE + kc]),
                              fb(Em[ar + kc + 4]), fb(Em[ar + 8 * SE + kc + 4]) };
#pragma unroll
            for (int j = 0; j < 8; j++) {
                const int br = (j * 8 + g) * SE;
                uint32_t bb[2] = { fb(En[br + kc]), fb(En[br + kc + 4]) };
                mma8(sc[j], a, bb);
            }
        }
#pragma unroll
        for (int j = 0; j < 8; j++) {
            rs0 += fmaxf(sc[j][0], 0.f) + fmaxf(sc[j][1], 0.f);
            rs1 += fmaxf(sc[j][2], 0.f) + fmaxf(sc[j][3], 0.f);
        }
        __syncthreads();
    }

    rs0 += __shfl_xor_sync(0xffffffffu, rs0, 1);
    rs0 += __shfl_xor_sync(0xffffffffu, rs0, 2);
    rs1 += __shfl_xor_sync(0xffffffffu, rs1, 1);
    rs1 += __shfl_xor_sync(0xffffffffu, rs1, 2);
    if (t == 0) {
        g_dinv[b * MESH + m0 + w * 16 + g]     = rsqrtf(1.f + rs0);
        g_dinv[b * MESH + m0 + w * 16 + g + 8] = rsqrtf(1.f + rs1);
    }
}

// ---------------------------------------------------------------------------
// Fused GCN layer: out = relu( [dinv ⊙ (relu(EE^T) @ (dinv⊙Y) + dinv⊙Y_m)] @ W^T )
// layer==0: Y = Xin, out -> g_H1.  layer==1: Y = g_H1, out -> Oout.
// ---------------------------------------------------------------------------
#define SM_FLOATS 26368  // 1024(dv) + max(3*4352 + 8704, 8448 + 16896)

__global__ __launch_bounds__(128) void k_layer(const float* __restrict__ emb,
                                               const float* __restrict__ Xin,
                                               const float* __restrict__ W,
                                               float* __restrict__ Oout,
                                               int layer) {
    extern __shared__ float smf[];
    float* dv = smf;                      // [1024]
    float* Em = smf + 1024;               // [TM*SE]
    float* En = smf + 1024 + 4352;        // [TN*SE]
    float* S  = smf + 1024 + 2 * 4352;    // [TM*SE]
    float* Xs = smf + 1024 + 3 * 4352;    // [TN*SX]
    float* T  = smf + 1024;               // [TM*STT]  (overlaps Em/En, phase 2)
    float* Wm = smf + 1024 + 8448;        // [DDIM*STT] (overlaps S/Xs, phase 2)

    const int b = blockIdx.y, m0 = blockIdx.x * TM;
    const int tid = threadIdx.x, w = tid >> 5, lane = tid & 31, g = lane >> 2, t = lane & 3;
    const float* Eb = emb + (size_t)b * MESH * EDIM;
    const float* Yb = (layer == 0 ? Xin : g_H1) + (size_t)b * MESH * DDIM;
    float* Ob = (layer == 0 ? g_H1 : Oout) + (size_t)b * MESH * DDIM;

    for (int i = tid; i < MESH; i += 128) dv[i] = g_dinv[b * MESH + i];
    for (int i = tid; i < TM * EDIM / 4; i += 128) {
        int r = i >> 4, c = (i & 15) << 2;
        float4 v = *reinterpret_cast<const float4*>(Eb + (m0 + r) * EDIM + c);
        *reinterpret_cast<float4*>(&Em[r * SE + c]) =
            make_float4(f2tf(v.x), f2tf(v.y), f2tf(v.z), f2tf(v.w));
    }

    float p[64];
#pragma unroll
    for (int i = 0; i < 64; i++) p[i] = 0.f;

    const int ar = (w * 16 + g) * SE;
    const int sr0 = (w * 16 + g) * SE, sr1 = (w * 16 + g + 8) * SE;

    for (int n0 = 0; n0 < MESH; n0 += TN) {
        for (int i = tid; i < TN * EDIM / 4; i += 128) {
            int r = i >> 4, c = (i & 15) << 2;
            float4 v = *reinterpret_cast<const float4*>(Eb + (n0 + r) * EDIM + c);
            *reinterpret_cast<float4*>(&En[r * SE + c]) =
                make_float4(f2tf(v.x), f2tf(v.y), f2tf(v.z), f2tf(v.w));
        }
        for (int i = tid; i < TN * DDIM / 4; i += 128) {
            int r = i >> 5, c = (i & 31) << 2;
            float4 v = *reinterpret_cast<const float4*>(Yb + (size_t)(n0 + r) * DDIM + c);
            float s = dv[n0 + r];
            *reinterpret_cast<float4*>(&Xs[r * SX + c]) =
                make_float4(f2tf(v.x * s), f2tf(v.y * s), f2tf(v.z * s), f2tf(v.w * s));
        }
        __syncthreads();

        // S = relu(Em @ En^T)  (each warp: 16 rows x 64 cols)
        float sc[8][4];
#pragma unroll
        for (int j = 0; j < 8; j++) { sc[j][0] = sc[j][1] = sc[j][2] = sc[j][3] = 0.f; }
#pragma unroll
        for (int k = 0; k < 8; k++) {
            const int kc = k * 8 + t;
            uint32_t a[4] = { fb(Em[ar + kc]), fb(Em[ar + 8 * SE + kc]),
                              fb(Em[ar + kc + 4]), fb(Em[ar + 8 * SE + kc + 4]) };
#pragma unroll
            for (int j = 0; j < 8; j++) {
                const int br = (j * 8 + g) * SE;
                uint32_t bb[2] = { fb(En[br + kc]), fb(En[br + kc + 4]) };
                mma8(sc[j], a, bb);
            }
        }
#pragma unroll
        for (int j = 0; j < 8; j++) {
            int c0 = j * 8 + 2 * t;
            *reinterpret_cast<float2*>(&S[sr0 + c0]) =
                make_float2(f2tf(fmaxf(sc[j][0], 0.f)), f2tf(fmaxf(sc[j][1], 0.f)));
            *reinterpret_cast<float2*>(&S[sr1 + c0]) =
                make_float2(f2tf(fmaxf(sc[j][2], 0.f)), f2tf(fmaxf(sc[j][3], 0.f)));
        }
        __syncwarp();  // S rows are warp-private: warp-level ordering suffices

        // P += S @ Xs  (each warp: 16 rows x 128 cols)
#pragma unroll
        for (int k = 0; k < 8; k++) {
            const int kc = k * 8 + t;
            uint32_t a[4] = { fb(S[sr0 + kc]), fb(S[sr1 + kc]),
                              fb(S[sr0 + kc + 4]), fb(S[sr1 + kc + 4]) };
#pragma unroll
            for (int j = 0; j < 16; j++) {
                uint32_t bb[2] = { fb(Xs[kc * SX + j * 8 + g]),
                                   fb(Xs[(kc + 4) * SX + j * 8 + g]) };
                mma8(&p[j * 4], a, bb);
            }
        }
        __syncthreads();
    }

    // Epilogue: T = dinv_m * (P + dinv_m * Y_m)  (tf32), then out = relu(T @ W^T)
    const int row0 = m0 + w * 16 + g;
    const float dm0 = dv[m0 + w * 16 + g], dm1 = dv[m0 + w * 16 + g + 8];
    const int tr0 = (w * 16 + g) * STT, tr1 = (w * 16 + g + 8) * STT;
#pragma unroll
    for (int j = 0; j < 16; j++) {
        int c0 = j * 8 + 2 * t;
        float2 y0 = *reinterpret_cast<const float2*>(Yb + (size_t)row0 * DDIM + c0);
        float2 y1 = *reinterpret_cast<const float2*>(Yb + (size_t)(row0 + 8) * DDIM + c0);
        *reinterpret_cast<float2*>(&T[tr0 + c0]) =
            make_float2(f2tf(dm0 * (p[j * 4 + 0] + dm0 * y0.x)),
                        f2tf(dm0 * (p[j * 4 + 1] + dm0 * y0.y)));
        *reinterpret_cast<float2*>(&T[tr1 + c0]) =
            make_float2(f2tf(dm1 * (p[j * 4 + 2] + dm1 * y1.x)),
                        f2tf(dm1 * (p[j * 4 + 3] + dm1 * y1.y)));
    }
    for (int i = tid; i < DDIM * DDIM / 4; i += 128) {
        int r = i >> 5, c = (i & 31) << 2;
        float4 v = *reinterpret_cast<const float4*>(W + r * DDIM + c);
        *reinterpret_cast<float4*>(&Wm[r * STT + c]) =
            make_float4(f2tf(v.x), f2tf(v.y), f2tf(v.z), f2tf(v.w));
    }
    __syncthreads();

#pragma unroll
    for (int i = 0; i < 64; i++) p[i] = 0.f;
#pragma unroll
    for (int k = 0; k < 16; k++) {
        const int kc = k * 8 + t;
        uint32_t a[4] = { fb(T[tr0 + kc]), fb(T[tr1 + kc]),
                          fb(T[tr0 + kc + 4]), fb(T[tr1 + kc + 4]) };
#pragma unroll
        for (int j = 0; j < 16; j++) {
            const int br = (j * 8 + g) * STT;
            uint32_t bb[2] = { fb(Wm[br + kc]), fb(Wm[br + kc + 4]) };
            mma8(&p[j * 4], a, bb);
        }
    }
#pragma unroll
    for (int j = 0; j < 16; j++) {
        int c0 = j * 8 + 2 * t;
        *reinterpret_cast<float2*>(Ob + (size_t)row0 * DDIM + c0) =
            make_float2(fmaxf(p[j * 4 + 0], 0.f), fmaxf(p[j * 4 + 1], 0.f));
        *reinterpret_cast<float2*>(Ob + (size_t)(row0 + 8) * DDIM + c0) =
            make_float2(fmaxf(p[j * 4 + 2], 0.f), fmaxf(p[j * 4 + 3], 0.f));
    }
}

extern "C" void kernel_launch(void* const* d_in, const int* in_sizes, int n_in,
                              void* d_out, int out_size) {
    (void)in_sizes; (void)n_in; (void)out_size;
    const float* X  = (const float*)d_in[0];
    const float* E  = (const float*)d_in[1];
    const float* W1 = (const float*)d_in[2];
    const float* W2 = (const float*)d_in[3];
    float* out = (float*)d_out;

    const size_t shm = SM_FLOATS * sizeof(float);  // 105472 B
    cudaFuncSetAttribute(k_layer, cudaFuncAttributeMaxDynamicSharedMemorySize, (int)shm);

    dim3 grid(MESH / TM, BATCH);
    k_dinv<<<grid, 128>>>(E);
    k_layer<<<grid, 128, shm>>>(E, X, W1, out, 0);
    k_layer<<<grid, 128, shm>>>(E, X, W2, out, 1);
}

// round 5
// speedup vs baseline: 1.5142x; 1.5142x over previous
#include <cuda_runtime.h>
#include <cstdint>

#define BATCH 32
#define MESH  1024
#define EDIM  64
#define DDIM  128
#define TM    64
#define KC    64
#define NCH   (MESH / KC)

#define SE  68   // stride: E/S tiles (a-frag + adj b-frag conflict-free)
#define SX  136  // stride: Ys tile (b-frag conflict-free: bank 8t+8j+g)
#define STT 132  // stride: T / W tiles in epilogue

__device__ float g_dinv[BATCH * MESH];
__device__ float g_Er[BATCH * MESH * EDIM];
__device__ float g_S[(size_t)BATCH * MESH * MESH];
__device__ float g_Ys[(size_t)BATCH * MESH * DDIM];
__device__ float g_H1[(size_t)BATCH * MESH * DDIM];

__device__ __forceinline__ float f2tf(float x) {
    uint32_t u;
    asm("cvt.rna.tf32.f32 %0, %1;" : "=r"(u) : "f"(x));
    return __uint_as_float(u);
}
__device__ __forceinline__ uint32_t fb(float x) { return __float_as_uint(x); }

// D(16x8,f32) += A(16x8,tf32,row) * B(8x8,tf32,col)
__device__ __forceinline__ void mma8(float* c, const uint32_t a[4], const uint32_t b[2]) {
    asm volatile(
        "mma.sync.aligned.m16n8k8.row.col.f32.tf32.tf32.f32 "
        "{%0,%1,%2,%3}, {%4,%5,%6,%7}, {%8,%9}, {%0,%1,%2,%3};"
        : "+f"(c[0]), "+f"(c[1]), "+f"(c[2]), "+f"(c[3])
        : "r"(a[0]), "r"(a[1]), "r"(a[2]), "r"(a[3]), "r"(b[0]), "r"(b[1]));
}

__device__ __forceinline__ void cpa16(float* dst, const float* src) {
    uint32_t d = (uint32_t)__cvta_generic_to_shared(dst);
    asm volatile("cp.async.cg.shared.global [%0], [%1], 16;" :: "r"(d), "l"(src));
}
__device__ __forceinline__ void cpa_commit() { asm volatile("cp.async.commit_group;"); }
template <int N>
__device__ __forceinline__ void cpa_wait() { asm volatile("cp.async.wait_group %0;" :: "n"(N)); }

// ---------------------------------------------------------------------------
// Round E to tf32 once (so later passes can cp.async raw bits).
// ---------------------------------------------------------------------------
__global__ __launch_bounds__(256) void k_pre(const float* __restrict__ E) {
    int i = blockIdx.x * 256 + threadIdx.x;  // float4 index; grid sized exactly
    float4 v = reinterpret_cast<const float4*>(E)[i];
    reinterpret_cast<float4*>(g_Er)[i] =
        make_float4(f2tf(v.x), f2tf(v.y), f2tf(v.z), f2tf(v.w));
}

// ---------------------------------------------------------------------------
// Ys = tf32(dinv[row] * Y[row][:]).  src: X (flag=0) or g_H1 (flag=1).
// ---------------------------------------------------------------------------
__global__ __launch_bounds__(256) void k_scale(const float* __restrict__ X, int fromH1) {
    const float* Y = fromH1 ? g_H1 : X;
    int i = blockIdx.x * 256 + threadIdx.x;  // float4 index (32 per row)
    float s = g_dinv[i >> 5];
    float4 v = reinterpret_cast<const float4*>(Y)[i];
    reinterpret_cast<float4*>(g_Ys)[i] =
        make_float4(f2tf(v.x * s), f2tf(v.y * s), f2tf(v.z * s), f2tf(v.w * s));
}

// ---------------------------------------------------------------------------
// k_adj: S[b] = tf32(relu(E E^T)) -> gmem, and dinv = rsqrt(1 + rowsum).
// CTA: 64 rows x full 1024 cols, 4 warps, warp tile 64x16.
// ---------------------------------------------------------------------------
#define ADJ_SMF (3 * TM * SE + 256)  // Em + En[2] + rsum

__global__ __launch_bounds__(128) void k_adj() {
    extern __shared__ float sm[];
    float* Em = sm;                       // [64][SE]
    float* En = sm + TM * SE;             // [2][64][SE]
    float* rsum = sm + 3 * TM * SE;       // [4][64]

    const int b = blockIdx.y, m0 = blockIdx.x * TM;
    const int tid = threadIdx.x, w = tid >> 5, lane = tid & 31, g = lane >> 2, t = lane & 3;
    const float* Eb = g_Er + (size_t)b * MESH * EDIM;

    for (int i = tid; i < TM * EDIM / 4; i += 128) {
        int r = i >> 4, c = (i & 15) << 2;
        *reinterpret_cast<float4*>(&Em[r * SE + c]) =
            *reinterpret_cast<const float4*>(Eb + (m0 + r) * EDIM + c);
    }

    auto loadEn = [&](int buf, int ch) {
        const float* src = Eb + ch * KC * EDIM;
        float* dst = En + buf * (TM * SE);
#pragma unroll
        for (int i = tid; i < KC * EDIM / 4; i += 128) {
            int r = i >> 4, c = (i & 15) << 2;
            cpa16(&dst[r * SE + c], src + r * EDIM + c);
        }
    };

    float rs0[4] = {0.f, 0.f, 0.f, 0.f}, rs1[4] = {0.f, 0.f, 0.f, 0.f};

    loadEn(0, 0); cpa_commit();
    for (int ch = 0; ch < NCH; ++ch) {
        if (ch + 1 < NCH) { loadEn((ch + 1) & 1, ch + 1); cpa_commit(); cpa_wait<1>(); }
        else cpa_wait<0>();
        __syncthreads();
        const float* Ec = En + (ch & 1) * (TM * SE);

        float acc[4][2][4];
#pragma unroll
        for (int rb = 0; rb < 4; rb++)
#pragma unroll
            for (int j = 0; j < 2; j++)
                acc[rb][j][0] = acc[rb][j][1] = acc[rb][j][2] = acc[rb][j][3] = 0.f;

#pragma unroll
        for (int k = 0; k < 8; k++) {
            const int kc = k * 8 + t;
            uint32_t a[4][4];
#pragma unroll
            for (int rb = 0; rb < 4; rb++) {
                const int ar = (rb * 16 + g) * SE;
                a[rb][0] = fb(Em[ar + kc]);
                a[rb][1] = fb(Em[ar + 8 * SE + kc]);
                a[rb][2] = fb(Em[ar + kc + 4]);
                a[rb][3] = fb(Em[ar + 8 * SE + kc + 4]);
            }
#pragma unroll
            for (int j = 0; j < 2; j++) {
                const int br = (w * 16 + j * 8 + g) * SE;
                uint32_t bb[2] = { fb(Ec[br + kc]), fb(Ec[br + kc + 4]) };
#pragma unroll
                for (int rb = 0; rb < 4; rb++) mma8(acc[rb][j], a[rb], bb);
            }
        }

        float* Sg = g_S + ((size_t)b * MESH + m0) * MESH + (size_t)ch * KC;
#pragma unroll
        for (int rb = 0; rb < 4; rb++) {
            const int row0 = rb * 16 + g, row1 = row0 + 8;
#pragma unroll
            for (int j = 0; j < 2; j++) {
                const int col = w * 16 + j * 8 + 2 * t;
                float v0 = fmaxf(acc[rb][j][0], 0.f), v1 = fmaxf(acc[rb][j][1], 0.f);
                float v2 = fmaxf(acc[rb][j][2], 0.f), v3 = fmaxf(acc[rb][j][3], 0.f);
                rs0[rb] += v0 + v1; rs1[rb] += v2 + v3;
                *reinterpret_cast<float2*>(Sg + (size_t)row0 * MESH + col) =
                    make_float2(f2tf(v0), f2tf(v1));
                *reinterpret_cast<float2*>(Sg + (size_t)row1 * MESH + col) =
                    make_float2(f2tf(v2), f2tf(v3));
            }
        }
        __syncthreads();
    }

#pragma unroll
    for (int rb = 0; rb < 4; rb++) {
        rs0[rb] += __shfl_xor_sync(0xffffffffu, rs0[rb], 1);
        rs0[rb] += __shfl_xor_sync(0xffffffffu, rs0[rb], 2);
        rs1[rb] += __shfl_xor_sync(0xffffffffu, rs1[rb], 1);
        rs1[rb] += __shfl_xor_sync(0xffffffffu, rs1[rb], 2);
    }
    if (t == 0) {
#pragma unroll
        for (int rb = 0; rb < 4; rb++) {
            rsum[w * 64 + rb * 16 + g] = rs0[rb];
            rsum[w * 64 + rb * 16 + g + 8] = rs1[rb];
        }
    }
    __syncthreads();
    if (tid < 64) {
        float d = 1.f + rsum[tid] + rsum[64 + tid] + rsum[128 + tid] + rsum[192 + tid];
        g_dinv[b * MESH + m0 + tid] = rsqrtf(d);
    }
}

// ---------------------------------------------------------------------------
// k_gemm: Out = relu( [dinv_m*(S@Ys + Ys_m)] @ W^T ).
// CTA: 64 rows x 128 cols, 4 warps, warp tile 64x32, K double-buffered.
// ---------------------------------------------------------------------------
#define GEMM_SMF (2 * TM * SE + 2 * KC * SX)  // 26112 floats = 104448 B

__global__ __launch_bounds__(128, 2) void k_gemm(const float* __restrict__ W,
                                                 float* __restrict__ OutExt,
                                                 int toH1) {
    extern __shared__ float sm[];
    float* Ss = sm;                    // [2][64][SE]
    float* Xs = sm + 2 * TM * SE;      // [2][64][SX]
    float* T  = sm;                    // [64][STT]   (epilogue overlap)
    float* Wm = sm + TM * STT;         // [128][STT]  (epilogue overlap)

    const int b = blockIdx.y, m0 = blockIdx.x * TM;
    const int tid = threadIdx.x, w = tid >> 5, lane = tid & 31, g = lane >> 2, t = lane & 3;
    const float* Sb = g_S + ((size_t)b * MESH + m0) * MESH;
    const float* Yb = g_Ys + (size_t)b * MESH * DDIM;
    float* Ob = (toH1 ? g_H1 : OutExt) + (size_t)b * MESH * DDIM;

    auto loadSs = [&](int buf, int ch) {
        const float* src = Sb + (size_t)ch * KC;
        float* dst = Ss + buf * (TM * SE);
#pragma unroll
        for (int i = tid; i < TM * KC / 4; i += 128) {
            int r = i >> 4, c = (i & 15) << 2;
            cpa16(&dst[r * SE + c], src + (size_t)r * MESH + c);
        }
    };
    auto loadXs = [&](int buf, int ch) {
        const float* src = Yb + (size_t)ch * KC * DDIM;
        float* dst = Xs + buf * (KC * SX);
#pragma unroll
        for (int i = tid; i < KC * DDIM / 4; i += 128) {
            int r = i >> 5, c = (i & 31) << 2;
            cpa16(&dst[r * SX + c], src + r * DDIM + c);
        }
    };

    float p[4][4][4];
#pragma unroll
    for (int rb = 0; rb < 4; rb++)
#pragma unroll
        for (int j = 0; j < 4; j++)
            p[rb][j][0] = p[rb][j][1] = p[rb][j][2] = p[rb][j][3] = 0.f;

    loadSs(0, 0); loadXs(0, 0); cpa_commit();
    for (int ch = 0; ch < NCH; ++ch) {
        if (ch + 1 < NCH) {
            loadSs((ch + 1) & 1, ch + 1);
            loadXs((ch + 1) & 1, ch + 1);
            cpa_commit(); cpa_wait<1>();
        } else cpa_wait<0>();
        __syncthreads();
        const float* Sc = Ss + (ch & 1) * (TM * SE);
        const float* Xc = Xs + (ch & 1) * (KC * SX);

#pragma unroll
        for (int k = 0; k < 8; k++) {
            const int kc = k * 8 + t;
            uint32_t a[4][4];
#pragma unroll
            for (int rb = 0; rb < 4; rb++) {
                const int ar = (rb * 16 + g) * SE;
                a[rb][0] = fb(Sc[ar + kc]);
                a[rb][1] = fb(Sc[ar + 8 * SE + kc]);
                a[rb][2] = fb(Sc[ar + kc + 4]);
                a[rb][3] = fb(Sc[ar + 8 * SE + kc + 4]);
            }
#pragma unroll
            for (int j = 0; j < 4; j++) {
                const int col = w * 32 + j * 8 + g;
                uint32_t bb[2] = { fb(Xc[kc * SX + col]), fb(Xc[(kc + 4) * SX + col]) };
#pragma unroll
                for (int rb = 0; rb < 4; rb++) mma8(p[rb][j], a[rb], bb);
            }
        }
        __syncthreads();
    }

    // Epilogue: T = tf32(dinv_m * (P + Ys_m)), then Out = relu(T @ W^T)
#pragma unroll
    for (int rb = 0; rb < 4; rb++) {
        const int row0 = rb * 16 + g, row1 = row0 + 8;
        const float dm0 = g_dinv[b * MESH + m0 + row0];
        const float dm1 = g_dinv[b * MESH + m0 + row1];
#pragma unroll
        for (int j = 0; j < 4; j++) {
            const int col = w * 32 + j * 8 + 2 * t;
            float2 y0 = *reinterpret_cast<const float2*>(Yb + (size_t)(m0 + row0) * DDIM + col);
            float2 y1 = *reinterpret_cast<const float2*>(Yb + (size_t)(m0 + row1) * DDIM + col);
            *reinterpret_cast<float2*>(&T[row0 * STT + col]) =
                make_float2(f2tf(dm0 * (p[rb][j][0] + y0.x)), f2tf(dm0 * (p[rb][j][1] + y0.y)));
            *reinterpret_cast<float2*>(&T[row1 * STT + col]) =
                make_float2(f2tf(dm1 * (p[rb][j][2] + y1.x)), f2tf(dm1 * (p[rb][j][3] + y1.y)));
        }
    }
    for (int i = tid; i < DDIM * DDIM / 4; i += 128) {
        int r = i >> 5, c = (i & 31) << 2;
        float4 v = *reinterpret_cast<const float4*>(W + r * DDIM + c);
        *reinterpret_cast<float4*>(&Wm[r * STT + c]) =
            make_float4(f2tf(v.x), f2tf(v.y), f2tf(v.z), f2tf(v.w));
    }
    __syncthreads();

#pragma unroll
    for (int rb = 0; rb < 4; rb++)
#pragma unroll
        for (int j = 0; j < 4; j++)
            p[rb][j][0] = p[rb][j][1] = p[rb][j][2] = p[rb][j][3] = 0.f;

#pragma unroll
    for (int k = 0; k < 16; k++) {
        const int kc = k * 8 + t;
        uint32_t a[4][4];
#pragma unroll
        for (int rb = 0; rb < 4; rb++) {
            const int ar = (rb * 16 + g) * STT;
            a[rb][0] = fb(T[ar + kc]);
            a[rb][1] = fb(T[ar + 8 * STT + kc]);
            a[rb][2] = fb(T[ar + kc + 4]);
            a[rb][3] = fb(T[ar + 8 * STT + kc + 4]);
        }
#pragma unroll
        for (int j = 0; j < 4; j++) {
            const int col = w * 32 + j * 8 + g;
            uint32_t bb[2] = { fb(Wm[col * STT + kc]), fb(Wm[col * STT + kc + 4]) };
#pragma unroll
            for (int rb = 0; rb < 4; rb++) mma8(p[rb][j], a[rb], bb);
        }
    }

#pragma unroll
    for (int rb = 0; rb < 4; rb++) {
        const int row0 = m0 + rb * 16 + g, row1 = row0 + 8;
#pragma unroll
        for (int j = 0; j < 4; j++) {
            const int col = w * 32 + j * 8 + 2 * t;
            *reinterpret_cast<float2*>(Ob + (size_t)row0 * DDIM + col) =
                make_float2(fmaxf(p[rb][j][0], 0.f), fmaxf(p[rb][j][1], 0.f));
            *reinterpret_cast<float2*>(Ob + (size_t)row1 * DDIM + col) =
                make_float2(fmaxf(p[rb][j][2], 0.f), fmaxf(p[rb][j][3], 0.f));
        }
    }
}

extern "C" void kernel_launch(void* const* d_in, const int* in_sizes, int n_in,
                              void* d_out, int out_size) {
    (void)in_sizes; (void)n_in; (void)out_size;
    const float* X  = (const float*)d_in[0];
    const float* E  = (const float*)d_in[1];
    const float* W1 = (const float*)d_in[2];
    const float* W2 = (const float*)d_in[3];
    float* out = (float*)d_out;

    cudaFuncSetAttribute(k_adj, cudaFuncAttributeMaxDynamicSharedMemorySize,
                         ADJ_SMF * (int)sizeof(float));
    cudaFuncSetAttribute(k_gemm, cudaFuncAttributeMaxDynamicSharedMemorySize,
                         GEMM_SMF * (int)sizeof(float));

    dim3 grid(MESH / TM, BATCH);
    k_pre<<<BATCH * MESH * EDIM / 4 / 256, 256>>>(E);
    k_adj<<<grid, 128, ADJ_SMF * sizeof(float)>>>();
    k_scale<<<BATCH * MESH * DDIM / 4 / 256, 256>>>(X, 0);
    k_gemm<<<grid, 128, GEMM_SMF * sizeof(float)>>>(W1, out, 1);
    k_scale<<<BATCH * MESH * DDIM / 4 / 256, 256>>>(X, 1);
    k_gemm<<<grid, 128, GEMM_SMF * sizeof(float)>>>(W2, out, 0);
}

// round 6
// speedup vs baseline: 2.1499x; 1.4198x over previous
#include <cuda_runtime.h>
#include <cuda_fp16.h>
#include <cstdint>

#define BATCH 32
#define MESH  1024
#define EDIM  64
#define DDIM  128
#define TM    64
#define KC    64
#define NCH   (MESH / KC)

#define SEW 36  // 4B-words per row: 64-half tiles (32 half2 + 4 pad) -> bank 4g+t
#define STW 68  // 4B-words per row: 128-half tiles (64 half2 + 4 pad) -> bank 4g+t

__device__ float  g_dinv[BATCH * MESH];
__device__ __half g_Eh[BATCH * MESH * EDIM];
__device__ __half g_Sh[(size_t)BATCH * MESH * MESH];
__device__ __half g_YsT[(size_t)BATCH * DDIM * MESH];   // [b][feat][node]
__device__ float  g_H1[(size_t)BATCH * MESH * DDIM];

__device__ __forceinline__ uint32_t h2u(__half2 h) { return *reinterpret_cast<uint32_t*>(&h); }

// D(16x8,f32) += A(16x16,f16,row) * B(16x8,f16,col)
__device__ __forceinline__ void mma16(float* c, const uint32_t a[4], uint32_t b0, uint32_t b1) {
    asm volatile(
        "mma.sync.aligned.m16n8k16.row.col.f32.f16.f16.f32 "
        "{%0,%1,%2,%3}, {%4,%5,%6,%7}, {%8,%9}, {%0,%1,%2,%3};"
        : "+f"(c[0]), "+f"(c[1]), "+f"(c[2]), "+f"(c[3])
        : "r"(a[0]), "r"(a[1]), "r"(a[2]), "r"(a[3]), "r"(b0), "r"(b1));
}

__device__ __forceinline__ void cpa16(uint32_t* dstWord, const void* src) {
    uint32_t d = (uint32_t)__cvta_generic_to_shared(dstWord);
    asm volatile("cp.async.cg.shared.global [%0], [%1], 16;" :: "r"(d), "l"(src));
}
__device__ __forceinline__ void cpa_commit() { asm volatile("cp.async.commit_group;"); }
template <int N>
__device__ __forceinline__ void cpa_wait() { asm volatile("cp.async.wait_group %0;" :: "n"(N)); }

// ---------------------------------------------------------------------------
// k_pre: E (f32) -> g_Eh (fp16, round-to-nearest)
// ---------------------------------------------------------------------------
__global__ __launch_bounds__(256) void k_pre(const float* __restrict__ E) {
    int i = blockIdx.x * 256 + threadIdx.x;  // float4 index, grid sized exactly
    float4 v = reinterpret_cast<const float4*>(E)[i];
    uint2 o;
    o.x = h2u(__floats2half2_rn(v.x, v.y));
    o.y = h2u(__floats2half2_rn(v.z, v.w));
    reinterpret_cast<uint2*>(g_Eh)[i] = o;
}

// ---------------------------------------------------------------------------
// k_scale: g_YsT[b][f][node] = fp16(dinv[node] * Y[node][f])   (transpose)
// ---------------------------------------------------------------------------
#define TSTR 72  // halves per feat row in transpose smem

__global__ __launch_bounds__(256) void k_scale(const float* __restrict__ X, int fromH1) {
    __shared__ __align__(16) __half smt[DDIM * TSTR];
    const int b = blockIdx.y, m0 = blockIdx.x * 64;
    const int tid = threadIdx.x;
    const float* Y = (fromH1 ? g_H1 : X) + ((size_t)b * MESH + m0) * DDIM;

#pragma unroll
    for (int it = 0; it < 8; it++) {
        int i = tid + it * 256;            // float4 over [64 nodes][128 feats]
        int node = i >> 5, fq = (i & 31) << 2;
        float s = g_dinv[b * MESH + m0 + node];
        float4 v = *reinterpret_cast<const float4*>(Y + (size_t)node * DDIM + fq);
        smt[(fq + 0) * TSTR + node] = __float2half_rn(v.x * s);
        smt[(fq + 1) * TSTR + node] = __float2half_rn(v.y * s);
        smt[(fq + 2) * TSTR + node] = __float2half_rn(v.z * s);
        smt[(fq + 3) * TSTR + node] = __float2half_rn(v.w * s);
    }
    __syncthreads();
    __half* Ob = g_YsT + (size_t)b * DDIM * MESH + m0;
#pragma unroll
    for (int it = 0; it < 4; it++) {
        int i = tid + it * 256;            // uint4 over [128 feats][64 halves]
        int f = i >> 3, c = (i & 7) << 3;
        *reinterpret_cast<uint4*>(Ob + (size_t)f * MESH + c) =
            *reinterpret_cast<const uint4*>(&smt[f * TSTR + c]);
    }
}

// ---------------------------------------------------------------------------
// k_adj: S[b] = fp16(relu(E E^T)) -> gmem, dinv = rsqrt(1 + rowsum).
// CTA 64 rows x 1024 cols (64-col chunks), 4 warps in 2x2, warp tile 32x32.
// ---------------------------------------------------------------------------
__global__ __launch_bounds__(128, 4) void k_adj() {
    __shared__ __align__(16) uint32_t Em[TM * SEW];
    __shared__ __align__(16) uint32_t En[2][TM * SEW];
    __shared__ float rsum[2][TM];

    const int b = blockIdx.y, m0 = blockIdx.x * TM;
    const int tid = threadIdx.x, w = tid >> 5, lane = tid & 31, g = lane >> 2, t = lane & 3;
    const int wr = w >> 1, wc = w & 1;
    const __half* Eb = g_Eh + (size_t)b * MESH * EDIM;

    for (int i = tid; i < 512; i += 128) {
        int r = i >> 3, c8 = i & 7;
        cpa16(&Em[r * SEW + c8 * 4], Eb + (m0 + r) * EDIM + c8 * 8);
    }
    auto loadEn = [&](int buf, int ch) {
        const __half* src = Eb + ch * KC * EDIM;
        uint32_t* dst = En[buf];
#pragma unroll
        for (int i = tid; i < 512; i += 128) {
            int r = i >> 3, c8 = i & 7;
            cpa16(&dst[r * SEW + c8 * 4], src + r * EDIM + c8 * 8);
        }
    };

    float rs0[2] = {0.f, 0.f}, rs1[2] = {0.f, 0.f};

    loadEn(0, 0); cpa_commit();
    for (int ch = 0; ch < NCH; ++ch) {
        if (ch + 1 < NCH) { loadEn((ch + 1) & 1, ch + 1); cpa_commit(); cpa_wait<1>(); }
        else cpa_wait<0>();
        __syncthreads();
        const uint32_t* Ec = En[ch & 1];

        float acc[2][4][4];
#pragma unroll
        for (int rb = 0; rb < 2; rb++)
#pragma unroll
            for (int j = 0; j < 4; j++)
                acc[rb][j][0] = acc[rb][j][1] = acc[rb][j][2] = acc[rb][j][3] = 0.f;

#pragma unroll
        for (int kk = 0; kk < 4; kk++) {
            uint32_t a[2][4];
#pragma unroll
            for (int rb = 0; rb < 2; rb++) {
                const int base = (wr * 32 + rb * 16 + g) * SEW + kk * 8 + t;
                a[rb][0] = Em[base];
                a[rb][1] = Em[base + 8 * SEW];
                a[rb][2] = Em[base + 4];
                a[rb][3] = Em[base + 8 * SEW + 4];
            }
#pragma unroll
            for (int j = 0; j < 4; j++) {
                const int bbase = (wc * 32 + j * 8 + g) * SEW + kk * 8 + t;
                uint32_t b0 = Ec[bbase], b1 = Ec[bbase + 4];
#pragma unroll
                for (int rb = 0; rb < 2; rb++) mma16(acc[rb][j], a[rb], b0, b1);
            }
        }

        __half* Sg = g_Sh + ((size_t)b * MESH + m0) * MESH + (size_t)ch * KC;
#pragma unroll
        for (int rb = 0; rb < 2; rb++) {
            const int row0 = wr * 32 + rb * 16 + g, row1 = row0 + 8;
#pragma unroll
            for (int j = 0; j < 4; j++) {
                const int col = wc * 32 + j * 8 + 2 * t;
                float v0 = fmaxf(acc[rb][j][0], 0.f), v1 = fmaxf(acc[rb][j][1], 0.f);
                float v2 = fmaxf(acc[rb][j][2], 0.f), v3 = fmaxf(acc[rb][j][3], 0.f);
                rs0[rb] += v0 + v1; rs1[rb] += v2 + v3;
                *reinterpret_cast<__half2*>(Sg + (size_t)row0 * MESH + col) =
                    __floats2half2_rn(v0, v1);
                *reinterpret_cast<__half2*>(Sg + (size_t)row1 * MESH + col) =
                    __floats2half2_rn(v2, v3);
            }
        }
        __syncthreads();
    }

#pragma unroll
    for (int rb = 0; rb < 2; rb++) {
        rs0[rb] += __shfl_xor_sync(0xffffffffu, rs0[rb], 1);
        rs0[rb] += __shfl_xor_sync(0xffffffffu, rs0[rb], 2);
        rs1[rb] += __shfl_xor_sync(0xffffffffu, rs1[rb], 1);
        rs1[rb] += __shfl_xor_sync(0xffffffffu, rs1[rb], 2);
    }
    if (t == 0) {
#pragma unroll
        for (int rb = 0; rb < 2; rb++) {
            rsum[wc][wr * 32 + rb * 16 + g]     = rs0[rb];
            rsum[wc][wr * 32 + rb * 16 + g + 8] = rs1[rb];
        }
    }
    __syncthreads();
    if (tid < TM) {
        float d = 1.f + rsum[0][tid] + rsum[1][tid];
        g_dinv[b * MESH + m0 + tid] = rsqrtf(d);
    }
}

// ---------------------------------------------------------------------------
// k_gemm: Out = relu( [dinv_m*(S@Ys) + dinv_m^2*Y_m] @ W^T ).
// CTA 64x128, 4 warps, warp tile 64x32, fp16 operands, K double-buffered.
// ---------------------------------------------------------------------------
#define GEMM_SMW (2 * TM * SEW + 2 * DDIM * SEW)  // 13824 words = 55296 B

__global__ __launch_bounds__(128, 3) void k_gemm(const float* __restrict__ Yraw,
                                                 const float* __restrict__ W,
                                                 float* __restrict__ Ob_base,
                                                 int layer) {
    extern __shared__ uint32_t smw[];
    uint32_t* Ss = smw;                    // [2][64][SEW]
    uint32_t* Xs = smw + 2 * TM * SEW;     // [2][128][SEW]
    uint32_t* T  = smw;                    // [64][STW]   (epilogue overlay)
    uint32_t* Wm = smw + TM * STW;         // [128][STW]  (epilogue overlay)

    const int b = blockIdx.y, m0 = blockIdx.x * TM;
    const int tid = threadIdx.x, w = tid >> 5, lane = tid & 31, g = lane >> 2, t = lane & 3;
    const __half* Sb = g_Sh + ((size_t)b * MESH + m0) * MESH;
    const __half* Tb = g_YsT + (size_t)b * DDIM * MESH;
    const float* Yb = Yraw + (size_t)b * MESH * DDIM;      // X or H1 (f32)
    float* Ob = Ob_base + (size_t)b * MESH * DDIM;

    auto loadSs = [&](int buf, int ch) {
        uint32_t* dst = Ss + buf * (TM * SEW);
#pragma unroll
        for (int i = tid; i < 512; i += 128) {
            int r = i >> 3, c8 = i & 7;
            cpa16(&dst[r * SEW + c8 * 4], Sb + (size_t)r * MESH + ch * KC + c8 * 8);
        }
    };
    auto loadXs = [&](int buf, int ch) {
        uint32_t* dst = Xs + buf * (DDIM * SEW);
#pragma unroll
        for (int i = tid; i < 1024; i += 128) {
            int r = i >> 3, c8 = i & 7;
            cpa16(&dst[r * SEW + c8 * 4], Tb + (size_t)r * MESH + ch * KC + c8 * 8);
        }
    };

    float p[4][4][4];
#pragma unroll
    for (int rb = 0; rb < 4; rb++)
#pragma unroll
        for (int j = 0; j < 4; j++)
            p[rb][j][0] = p[rb][j][1] = p[rb][j][2] = p[rb][j][3] = 0.f;

    loadSs(0, 0); loadXs(0, 0); cpa_commit();
    for (int ch = 0; ch < NCH; ++ch) {
        if (ch + 1 < NCH) {
            loadSs((ch + 1) & 1, ch + 1);
            loadXs((ch + 1) & 1, ch + 1);
            cpa_commit(); cpa_wait<1>();
        } else cpa_wait<0>();
        __syncthreads();
        const uint32_t* Sc = Ss + (ch & 1) * (TM * SEW);
        const uint32_t* Xc = Xs + (ch & 1) * (DDIM * SEW);

#pragma unroll
        for (int kk = 0; kk < 4; kk++) {
            uint32_t a[4][4];
#pragma unroll
            for (int rb = 0; rb < 4; rb++) {
                const int base = (rb * 16 + g) * SEW + kk * 8 + t;
                a[rb][0] = Sc[base];
                a[rb][1] = Sc[base + 8 * SEW];
                a[rb][2] = Sc[base + 4];
                a[rb][3] = Sc[base + 8 * SEW + 4];
            }
#pragma unroll
            for (int j = 0; j < 4; j++) {
                const int bbase = (w * 32 + j * 8 + g) * SEW + kk * 8 + t;
                uint32_t b0 = Xc[bbase], b1 = Xc[bbase + 4];
#pragma unroll
                for (int rb = 0; rb < 4; rb++) mma16(p[rb][j], a[rb], b0, b1);
            }
        }
        __syncthreads();
    }

    // Epilogue: T = fp16(dm*P + dm^2*Y_m), then Out = relu(T @ W^T)
#pragma unroll
    for (int rb = 0; rb < 4; rb++) {
        const int row0 = rb * 16 + g, row1 = row0 + 8;
        const float dm0 = g_dinv[b * MESH + m0 + row0];
        const float dm1 = g_dinv[b * MESH + m0 + row1];
#pragma unroll
        for (int j = 0; j < 4; j++) {
            const int col = w * 32 + j * 8 + 2 * t;
            float2 y0 = *reinterpret_cast<const float2*>(Yb + (size_t)(m0 + row0) * DDIM + col);
            float2 y1 = *reinterpret_cast<const float2*>(Yb + (size_t)(m0 + row1) * DDIM + col);
            T[row0 * STW + 16 * w + 4 * j + t] =
                h2u(__floats2half2_rn(dm0 * (p[rb][j][0] + dm0 * y0.x),
                                      dm0 * (p[rb][j][1] + dm0 * y0.y)));
            T[row1 * STW + 16 * w + 4 * j + t] =
                h2u(__floats2half2_rn(dm1 * (p[rb][j][2] + dm1 * y1.x),
                                      dm1 * (p[rb][j][3] + dm1 * y1.y)));
        }
    }
    for (int i = tid; i < DDIM * 64; i += 128) {
        int r = i >> 6, c = i & 63;
        float2 wv = *reinterpret_cast<const float2*>(W + r * DDIM + 2 * c);
        Wm[r * STW + c] = h2u(__floats2half2_rn(wv.x, wv.y));
    }
    __syncthreads();

#pragma unroll
    for (int rb = 0; rb < 4; rb++)
#pragma unroll
        for (int j = 0; j < 4; j++)
            p[rb][j][0] = p[rb][j][1] = p[rb][j][2] = p[rb][j][3] = 0.f;

#pragma unroll
    for (int kk = 0; kk < 8; kk++) {
        uint32_t a[4][4];
#pragma unroll
        for (int rb = 0; rb < 4; rb++) {
            const int base = (rb * 16 + g) * STW + kk * 8 + t;
            a[rb][0] = T[base];
            a[rb][1] = T[base + 8 * STW];
            a[rb][2] = T[base + 4];
            a[rb][3] = T[base + 8 * STW + 4];
        }
#pragma unroll
        for (int j = 0; j < 4; j++) {
            const int bbase = (w * 32 + j * 8 + g) * STW + kk * 8 + t;
            uint32_t b0 = Wm[bbase], b1 = Wm[bbase + 4];
#pragma unroll
            for (int rb = 0; rb < 4; rb++) mma16(p[rb][j], a[rb], b0, b1);
        }
    }

#pragma unroll
    for (int rb = 0; rb < 4; rb++) {
        const int row0 = m0 + rb * 16 + g, row1 = row0 + 8;
#pragma unroll
        for (int j = 0; j < 4; j++) {
            const int col = w * 32 + j * 8 + 2 * t;
            *reinterpret_cast<float2*>(Ob + (size_t)row0 * DDIM + col) =
                make_float2(fmaxf(p[rb][j][0], 0.f), fmaxf(p[rb][j][1], 0.f));
            *reinterpret_cast<float2*>(Ob + (size_t)row1 * DDIM + col) =
                make_float2(fmaxf(p[rb][j][2], 0.f), fmaxf(p[rb][j][3], 0.f));
        }
    }
}

extern "C" void kernel_launch(void* const* d_in, const int* in_sizes, int n_in,
                              void* d_out, int out_size) {
    (void)in_sizes; (void)n_in; (void)out_size;
    const float* X  = (const float*)d_in[0];
    const float* E  = (const float*)d_in[1];
    const float* W1 = (const float*)d_in[2];
    const float* W2 = (const float*)d_in[3];
    float* out = (float*)d_out;

    cudaFuncSetAttribute(k_gemm, cudaFuncAttributeMaxDynamicSharedMemorySize,
                         GEMM_SMW * (int)sizeof(uint32_t));

    float* H1;
    cudaGetSymbolAddress((void**)&H1, g_H1);

    dim3 grid(MESH / TM, BATCH);
    dim3 sgrid(MESH / 64, BATCH);
    k_pre<<<BATCH * MESH * EDIM / 4 / 256, 256>>>(E);
    k_adj<<<grid, 128>>>();
    k_scale<<<sgrid, 256>>>(X, 0);
    k_gemm<<<grid, 128, GEMM_SMW * sizeof(uint32_t)>>>(X, W1, H1, 0);
    k_scale<<<sgrid, 256>>>(X, 1);
    k_gemm<<<grid, 128, GEMM_SMW * sizeof(uint32_t)>>>(H1, W2, out, 1);
}

// round 11
// speedup vs baseline: 2.1995x; 1.0231x over previous
#include <cuda_runtime.h>
#include <cuda_fp16.h>
#include <cstdint>

#define BATCH 32
#define MESH  1024
#define EDIM  64
#define DDIM  128
#define TM    64
#define KC    64
#define NCH   (MESH / KC)

#define SEW 36  // words per row, 64-half tiles (144 B): ldmatrix conflict-free
#define STW 68  // words per row, 128-half tiles (272 B): ldmatrix conflict-free

__device__ float  g_dinv[BATCH * MESH];
__device__ __half g_Eh[BATCH * MESH * EDIM];
__device__ __half g_Sh[(size_t)BATCH * MESH * MESH];
__device__ __half g_YsT[(size_t)BATCH * DDIM * MESH];   // [b][feat][node]
__device__ float  g_H1[(size_t)BATCH * MESH * DDIM];

__device__ __forceinline__ uint32_t h2u(__half2 h) { return *reinterpret_cast<uint32_t*>(&h); }

// D(16x8,f32) += A(16x16,f16,row) * B(16x8,f16,col)
__device__ __forceinline__ void mma16(float* c, const uint32_t a[4], uint32_t b0, uint32_t b1) {
    asm volatile(
        "mma.sync.aligned.m16n8k16.row.col.f32.f16.f16.f32 "
        "{%0,%1,%2,%3}, {%4,%5,%6,%7}, {%8,%9}, {%0,%1,%2,%3};"
        : "+f"(c[0]), "+f"(c[1]), "+f"(c[2]), "+f"(c[3])
        : "r"(a[0]), "r"(a[1]), "r"(a[2]), "r"(a[3]), "r"(b0), "r"(b1));
}

__device__ __forceinline__ void ldsm4(uint32_t* r, uint32_t addr) {
    asm volatile("ldmatrix.sync.aligned.m8n8.x4.shared.b16 {%0,%1,%2,%3}, [%4];"
                 : "=r"(r[0]), "=r"(r[1]), "=r"(r[2]), "=r"(r[3]) : "r"(addr));
}

__device__ __forceinline__ uint32_t smem_u32(const void* p) {
    return (uint32_t)__cvta_generic_to_shared(p);
}
__device__ __forceinline__ void cpa16(void* dst, const void* src) {
    uint32_t d = (uint32_t)__cvta_generic_to_shared(dst);
    asm volatile("cp.async.cg.shared.global [%0], [%1], 16;" :: "r"(d), "l"(src));
}
__device__ __forceinline__ void cpa_commit() { asm volatile("cp.async.commit_group;"); }
template <int N>
__device__ __forceinline__ void cpa_wait() { asm volatile("cp.async.wait_group %0;" :: "n"(N)); }

// ---------------------------------------------------------------------------
// k_pre: E (f32) -> g_Eh (fp16)
// ---------------------------------------------------------------------------
__global__ __launch_bounds__(256) void k_pre(const float* __restrict__ E) {
    int i = blockIdx.x * 256 + threadIdx.x;
    float4 v = reinterpret_cast<const float4*>(E)[i];
    uint2 o;
    o.x = h2u(__floats2half2_rn(v.x, v.y));
    o.y = h2u(__floats2half2_rn(v.z, v.w));
    reinterpret_cast<uint2*>(g_Eh)[i] = o;
}

// ---------------------------------------------------------------------------
// k_scale: g_YsT[b][f][node] = fp16(dinv[node] * Y[node][f])   (transpose)
// ---------------------------------------------------------------------------
#define TSTR 72

__global__ __launch_bounds__(256) void k_scale(const float* __restrict__ X, int fromH1) {
    __shared__ __align__(16) __half smt[DDIM * TSTR];
    const int b = blockIdx.y, m0 = blockIdx.x * 64;
    const int tid = threadIdx.x;
    const float* Y = (fromH1 ? g_H1 : X) + ((size_t)b * MESH + m0) * DDIM;

#pragma unroll
    for (int it = 0; it < 8; it++) {
        int i = tid + it * 256;
        int node = i >> 5, fq = (i & 31) << 2;
        float s = g_dinv[b * MESH + m0 + node];
        float4 v = *reinterpret_cast<const float4*>(Y + (size_t)node * DDIM + fq);
        smt[(fq + 0) * TSTR + node] = __float2half_rn(v.x * s);
        smt[(fq + 1) * TSTR + node] = __float2half_rn(v.y * s);
        smt[(fq + 2) * TSTR + node] = __float2half_rn(v.z * s);
        smt[(fq + 3) * TSTR + node] = __float2half_rn(v.w * s);
    }
    __syncthreads();
    __half* Ob = g_YsT + (size_t)b * DDIM * MESH + m0;
#pragma unroll
    for (int it = 0; it < 4; it++) {
        int i = tid + it * 256;
        int f = i >> 3, c = (i & 7) << 3;
        *reinterpret_cast<uint4*>(Ob + (size_t)f * MESH + c) =
            *reinterpret_cast<const uint4*>(&smt[f * TSTR + c]);
    }
}

// ---------------------------------------------------------------------------
// k_adj: S[b] = fp16(relu(E E^T)) -> gmem, dinv = rsqrt(1 + rowsum).
// CTA 64 rows x 1024 cols, 4 warps 2x2, warp tile 32x32.  ldmatrix frags.
// ---------------------------------------------------------------------------
__global__ __launch_bounds__(128, 4) void k_adj() {
    __shared__ __align__(16) uint32_t Em[TM * SEW];
    __shared__ __align__(16) uint32_t En[2][TM * SEW];
    __shared__ float rsum[2][TM];

    const int b = blockIdx.y, m0 = blockIdx.x * TM;
    const int tid = threadIdx.x, w = tid >> 5, lane = tid & 31, g = lane >> 2, t = lane & 3;
    const int wr = w >> 1, wc = w & 1;
    const __half* Eb = g_Eh + (size_t)b * MESH * EDIM;

    // ldmatrix per-lane offsets (byte), row stride 144 B
    const uint32_t aOff = (lane & 15) * 144 + (lane >> 4) * 16;
    const uint32_t bOff = ((lane & 7) + ((lane >> 4) << 3)) * 144 + ((lane >> 3) & 1) * 16;
    const uint32_t sEm = smem_u32(Em), sEn = smem_u32(En);

    for (int i = tid; i < 512; i += 128) {
        int r = i >> 3, c8 = i & 7;
        cpa16(&Em[r * SEW + c8 * 4], Eb + (m0 + r) * EDIM + c8 * 8);
    }
    auto loadEn = [&](int buf, int ch) {
        const __half* src = Eb + ch * KC * EDIM;
        uint32_t* dst = En[buf];
#pragma unroll
        for (int i = tid; i < 512; i += 128) {
            int r = i >> 3, c8 = i & 7;
            cpa16(&dst[r * SEW + c8 * 4], src + r * EDIM + c8 * 8);
        }
    };

    float rs0[2] = {0.f, 0.f}, rs1[2] = {0.f, 0.f};

    loadEn(0, 0); cpa_commit();
    for (int ch = 0; ch < NCH; ++ch) {
        if (ch + 1 < NCH) { loadEn((ch + 1) & 1, ch + 1); cpa_commit(); cpa_wait<1>(); }
        else cpa_wait<0>();
        __syncthreads();
        const uint32_t sEc = sEn + (ch & 1) * (TM * SEW * 4);

        float acc[2][4][4];
#pragma unroll
        for (int rb = 0; rb < 2; rb++)
#pragma unroll
            for (int j = 0; j < 4; j++)
                acc[rb][j][0] = acc[rb][j][1] = acc[rb][j][2] = acc[rb][j][3] = 0.f;

#pragma unroll
        for (int kk = 0; kk < 4; kk++) {
            uint32_t a[2][4], bb[2][4];
#pragma unroll
            for (int rb = 0; rb < 2; rb++)
                ldsm4(a[rb], sEm + aOff + (wr * 32 + rb * 16) * 144 + kk * 32);
#pragma unroll
            for (int j2 = 0; j2 < 2; j2++)
                ldsm4(bb[j2], sEc + bOff + (wc * 32 + j2 * 16) * 144 + kk * 32);
#pragma unroll
            for (int j2 = 0; j2 < 2; j2++)
#pragma unroll
                for (int rb = 0; rb < 2; rb++) {
                    mma16(acc[rb][2 * j2],     a[rb], bb[j2][0], bb[j2][1]);
                    mma16(acc[rb][2 * j2 + 1], a[rb], bb[j2][2], bb[j2][3]);
                }
        }

        __half* Sg = g_Sh + ((size_t)b * MESH + m0) * MESH + (size_t)ch * KC;
#pragma unroll
        for (int rb = 0; rb < 2; rb++) {
            const int row0 = wr * 32 + rb * 16 + g, row1 = row0 + 8;
#pragma unroll
            for (int j = 0; j < 4; j++) {
                const int col = wc * 32 + j * 8 + 2 * t;
                float v0 = fmaxf(acc[rb][j][0], 0.f), v1 = fmaxf(acc[rb][j][1], 0.f);
                float v2 = fmaxf(acc[rb][j][2], 0.f), v3 = fmaxf(acc[rb][j][3], 0.f);
                rs0[rb] += v0 + v1; rs1[rb] += v2 + v3;
                *reinterpret_cast<__half2*>(Sg + (size_t)row0 * MESH + col) =
                    __floats2half2_rn(v0, v1);
                *reinterpret_cast<__half2*>(Sg + (size_t)row1 * MESH + col) =
                    __floats2half2_rn(v2, v3);
            }
        }
        __syncthreads();
    }

#pragma unroll
    for (int rb = 0; rb < 2; rb++) {
        rs0[rb] += __shfl_xor_sync(0xffffffffu, rs0[rb], 1);
        rs0[rb] += __shfl_xor_sync(0xffffffffu, rs0[rb], 2);
        rs1[rb] += __shfl_xor_sync(0xffffffffu, rs1[rb], 1);
        rs1[rb] += __shfl_xor_sync(0xffffffffu, rs1[rb], 2);
    }
    if (t == 0) {
#pragma unroll
        for (int rb = 0; rb < 2; rb++) {
            rsum[wc][wr * 32 + rb * 16 + g]     = rs0[rb];
            rsum[wc][wr * 32 + rb * 16 + g + 8] = rs1[rb];
        }
    }
    __syncthreads();
    if (tid < TM) {
        float d = 1.f + rsum[0][tid] + rsum[1][tid];
        g_dinv[b * MESH + m0 + tid] = rsqrtf(d);
    }
}

// ---------------------------------------------------------------------------
// k_gemm: Out = relu( [dinv_m*(S@Ys) + dinv_m^2*Y_m] @ W^T ).
// CTA 64x128, 4 warps, warp tile 64x32, ldmatrix frags, K double-buffered.
// ---------------------------------------------------------------------------
#define GEMM_SMW (2 * TM * SEW + 2 * DDIM * SEW)  // 13824 words = 55296 B

__global__ __launch_bounds__(128, 3) void k_gemm(const float* __restrict__ Yraw,
                                                 const float* __restrict__ W,
                                                 float* __restrict__ Ob_base,
                                                 int layer) {
    extern __shared__ uint32_t smw[];
    uint32_t* Ss = smw;                    // [2][64][SEW]
    uint32_t* Xs = smw + 2 * TM * SEW;     // [2][128][SEW]
    uint32_t* T  = smw;                    // [64][STW]   (epilogue overlay)
    uint32_t* Wm = smw + TM * STW;         // [128][STW]  (epilogue overlay)

    const int b = blockIdx.y, m0 = blockIdx.x * TM;
    const int tid = threadIdx.x, w = tid >> 5, lane = tid & 31, g = lane >> 2, t = lane & 3;
    const __half* Sb = g_Sh + ((size_t)b * MESH + m0) * MESH;
    const __half* Tb = g_YsT + (size_t)b * DDIM * MESH;
    const float* Yb = Yraw + (size_t)b * MESH * DDIM;
    float* Ob = Ob_base + (size_t)b * MESH * DDIM;

    // ldmatrix per-lane offsets: mainloop stride 144 B, epilogue stride 272 B
    const uint32_t aOff  = (lane & 15) * 144 + (lane >> 4) * 16;
    const uint32_t bOff  = ((lane & 7) + ((lane >> 4) << 3)) * 144 + ((lane >> 3) & 1) * 16;
    const uint32_t aOffE = (lane & 15) * 272 + (lane >> 4) * 16;
    const uint32_t bOffE = ((lane & 7) + ((lane >> 4) << 3)) * 272 + ((lane >> 3) & 1) * 16;
    const uint32_t sS0 = smem_u32(Ss), sX0 = smem_u32(Xs);
    const uint32_t sT = smem_u32(T), sW = smem_u32(Wm);

    auto loadSs = [&](int buf, int ch) {
        uint32_t* dst = Ss + buf * (TM * SEW);
#pragma unroll
        for (int i = tid; i < 512; i += 128) {
            int r = i >> 3, c8 = i & 7;
            cpa16(&dst[r * SEW + c8 * 4], Sb + (size_t)r * MESH + ch * KC + c8 * 8);
        }
    };
    auto loadXs = [&](int buf, int ch) {
        uint32_t* dst = Xs + buf * (DDIM * SEW);
#pragma unroll
        for (int i = tid; i < 1024; i += 128) {
            int r = i >> 3, c8 = i & 7;
            cpa16(&dst[r * SEW + c8 * 4], Tb + (size_t)r * MESH + ch * KC + c8 * 8);
        }
    };

    float p[4][4][4];
#pragma unroll
    for (int rb = 0; rb < 4; rb++)
#pragma unroll
        for (int j = 0; j < 4; j++)
            p[rb][j][0] = p[rb][j][1] = p[rb][j][2] = p[rb][j][3] = 0.f;

    loadSs(0, 0); loadXs(0, 0); cpa_commit();
    for (int ch = 0; ch < NCH; ++ch) {
        if (ch + 1 < NCH) {
            loadSs((ch + 1) & 1, ch + 1);
            loadXs((ch + 1) & 1, ch + 1);
            cpa_commit(); cpa_wait<1>();
        } else cpa_wait<0>();
        __syncthreads();
        const uint32_t sA = sS0 + (ch & 1) * (TM * SEW * 4);
        const uint32_t sB = sX0 + (ch & 1) * (DDIM * SEW * 4) + w * 32 * 144;

#pragma unroll
        for (int kk = 0; kk < 4; kk++) {
            uint32_t a[4][4], bb[2][4];
#pragma unroll
            for (int rb = 0; rb < 4; rb++)
                ldsm4(a[rb], sA + aOff + rb * 16 * 144 + kk * 32);
#pragma unroll
            for (int j2 = 0; j2 < 2; j2++)
                ldsm4(bb[j2], sB + bOff + j2 * 16 * 144 + kk * 32);
#pragma unroll
            for (int j2 = 0; j2 < 2; j2++)
#pragma unroll
                for (int rb = 0; rb < 4; rb++) {
                    mma16(p[rb][2 * j2],     a[rb], bb[j2][0], bb[j2][1]);
                    mma16(p[rb][2 * j2 + 1], a[rb], bb[j2][2], bb[j2][3]);
                }
        }
        __syncthreads();
    }

    // Epilogue: T = fp16(dm*P + dm^2*Y_m), then Out = relu(T @ W^T)
#pragma unroll
    for (int rb = 0; rb < 4; rb++) {
        const int row0 = rb * 16 + g, row1 = row0 + 8;
        const float dm0 = g_dinv[b * MESH + m0 + row0];
        const float dm1 = g_dinv[b * MESH + m0 + row1];
#pragma unroll
        for (int j = 0; j < 4; j++) {
            const int col = w * 32 + j * 8 + 2 * t;
            float2 y0 = *reinterpret_cast<const float2*>(Yb + (size_t)(m0 + row0) * DDIM + col);
            float2 y1 = *reinterpret_cast<const float2*>(Yb + (size_t)(m0 + row1) * DDIM + col);
            T[row0 * STW + 16 * w + 4 * j + t] =
                h2u(__floats2half2_rn(dm0 * (p[rb][j][0] + dm0 * y0.x),
                                      dm0 * (p[rb][j][1] + dm0 * y0.y)));
            T[row1 * STW + 16 * w + 4 * j + t] =
                h2u(__floats2half2_rn(dm1 * (p[rb][j][2] + dm1 * y1.x),
                                      dm1 * (p[rb][j][3] + dm1 * y1.y)));
        }
    }
    for (int i = tid; i < DDIM * 64; i += 128) {
        int r = i >> 6, c = i & 63;
        float2 wv = *reinterpret_cast<const float2*>(W + r * DDIM + 2 * c);
        Wm[r * STW + c] = h2u(__floats2half2_rn(wv.x, wv.y));
    }
    __syncthreads();

#pragma unroll
    for (int rb = 0; rb < 4; rb++)
#pragma unroll
        for (int j = 0; j < 4; j++)
            p[rb][j][0] = p[rb][j][1] = p[rb][j][2] = p[rb][j][3] = 0.f;

#pragma unroll
    for (int kk = 0; kk < 8; kk++) {
        uint32_t a[4][4], bb[2][4];
#pragma unroll
        for (int rb = 0; rb < 4; rb++)
            ldsm4(a[rb], sT + aOffE + rb * 16 * 272 + kk * 32);
#pragma unroll
        for (int j2 = 0; j2 < 2; j2++)
            ldsm4(bb[j2], sW + bOffE + (w * 32 + j2 * 16) * 272 + kk * 32);
#pragma unroll
        for (int j2 = 0; j2 < 2; j2++)
#pragma unroll
            for (int rb = 0; rb < 4; rb++) {
                mma16(p[rb][2 * j2],     a[rb], bb[j2][0], bb[j2][1]);
                mma16(p[rb][2 * j2 + 1], a[rb], bb[j2][2], bb[j2][3]);
            }
    }

#pragma unroll
    for (int rb = 0; rb < 4; rb++) {
        const int row0 = m0 + rb * 16 + g, row1 = row0 + 8;
#pragma unroll
        for (int j = 0; j < 4; j++) {
            const int col = w * 32 + j * 8 + 2 * t;
            *reinterpret_cast<float2*>(Ob + (size_t)row0 * DDIM + col) =
                make_float2(fmaxf(p[rb][j][0], 0.f), fmaxf(p[rb][j][1], 0.f));
            *reinterpret_cast<float2*>(Ob + (size_t)row1 * DDIM + col) =
                make_float2(fmaxf(p[rb][j][2], 0.f), fmaxf(p[rb][j][3], 0.f));
        }
    }
}

extern "C" void kernel_launch(void* const* d_in, const int* in_sizes, int n_in,
                              void* d_out, int out_size) {
    (void)in_sizes; (void)n_in; (void)out_size;
    const float* X  = (const float*)d_in[0];
    const float* E  = (const float*)d_in[1];
    const float* W1 = (const float*)d_in[2];
    const float* W2 = (const float*)d_in[3];
    float* out = (float*)d_out;

    cudaFuncSetAttribute(k_gemm, cudaFuncAttributeMaxDynamicSharedMemorySize,
                         GEMM_SMW * (int)sizeof(uint32_t));

    float* H1;
    cudaGetSymbolAddress((void**)&H1, g_H1);

    dim3 grid(MESH / TM, BATCH);
    dim3 sgrid(MESH / 64, BATCH);
    k_pre<<<BATCH * MESH * EDIM / 4 / 256, 256>>>(E);
    k_adj<<<grid, 128>>>();
    k_scale<<<sgrid, 256>>>(X, 0);
    k_gemm<<<grid, 128, GEMM_SMW * sizeof(uint32_t)>>>(X, W1, H1, 0);
    k_scale<<<sgrid, 256>>>(X, 1);
    k_gemm<<<grid, 128, GEMM_SMW * sizeof(uint32_t)>>>(H1, W2, out, 1);
}

// round 12
// speedup vs baseline: 2.2283x; 1.0131x over previous
#include <cuda_runtime.h>
#include <cuda_fp16.h>
#include <cstdint>

#define BATCH 32
#define MESH  1024
#define EDIM  64
#define DDIM  128
#define TM    64
#define KC    64
#define NCH   (MESH / KC)

#define SEW 36  // words per row, 64-half tiles (144 B): ldmatrix conflict-free
#define STW 68  // words per row, 128-half tiles (272 B): ldmatrix conflict-free

__device__ float  g_dinv[BATCH * MESH];
__device__ __half g_Eh[BATCH * MESH * EDIM];
__device__ __half g_Sh[(size_t)BATCH * MESH * MESH];
__device__ __half g_YsT[(size_t)BATCH * DDIM * MESH];   // [b][feat][node]
__device__ float  g_H1[(size_t)BATCH * MESH * DDIM];

__device__ __forceinline__ uint32_t h2u(__half2 h) { return *reinterpret_cast<uint32_t*>(&h); }

// D(16x8,f32) += A(16x16,f16,row) * B(16x8,f16,col)
__device__ __forceinline__ void mma16(float* c, const uint32_t a[4], uint32_t b0, uint32_t b1) {
    asm volatile(
        "mma.sync.aligned.m16n8k16.row.col.f32.f16.f16.f32 "
        "{%0,%1,%2,%3}, {%4,%5,%6,%7}, {%8,%9}, {%0,%1,%2,%3};"
        : "+f"(c[0]), "+f"(c[1]), "+f"(c[2]), "+f"(c[3])
        : "r"(a[0]), "r"(a[1]), "r"(a[2]), "r"(a[3]), "r"(b0), "r"(b1));
}

__device__ __forceinline__ void ldsm4(uint32_t* r, uint32_t addr) {
    asm volatile("ldmatrix.sync.aligned.m8n8.x4.shared.b16 {%0,%1,%2,%3}, [%4];"
                 : "=r"(r[0]), "=r"(r[1]), "=r"(r[2]), "=r"(r[3]) : "r"(addr));
}

__device__ __forceinline__ uint32_t smem_u32(const void* p) {
    return (uint32_t)__cvta_generic_to_shared(p);
}
__device__ __forceinline__ void cpa16(void* dst, const void* src) {
    uint32_t d = (uint32_t)__cvta_generic_to_shared(dst);
    asm volatile("cp.async.cg.shared.global [%0], [%1], 16;" :: "r"(d), "l"(src));
}
__device__ __forceinline__ void cpa_commit() { asm volatile("cp.async.commit_group;"); }
template <int N>
__device__ __forceinline__ void cpa_wait() { asm volatile("cp.async.wait_group %0;" :: "n"(N)); }

// ---------------------------------------------------------------------------
// k_pre: E (f32) -> g_Eh (fp16)
// ---------------------------------------------------------------------------
__global__ __launch_bounds__(256) void k_pre(const float* __restrict__ E) {
    int i = blockIdx.x * 256 + threadIdx.x;
    float4 v = reinterpret_cast<const float4*>(E)[i];
    uint2 o;
    o.x = h2u(__floats2half2_rn(v.x, v.y));
    o.y = h2u(__floats2half2_rn(v.z, v.w));
    reinterpret_cast<uint2*>(g_Eh)[i] = o;
}

// ---------------------------------------------------------------------------
// k_scale: g_YsT[b][f][node] = fp16(dinv[node] * Y[node][f])  (layer-2 only)
// ---------------------------------------------------------------------------
#define TSTR 72

__global__ __launch_bounds__(256) void k_scale(int fromH1_unused) {
    __shared__ __align__(16) __half smt[DDIM * TSTR];
    const int b = blockIdx.y, m0 = blockIdx.x * 64;
    const int tid = threadIdx.x;
    const float* Y = g_H1 + ((size_t)b * MESH + m0) * DDIM;

#pragma unroll
    for (int it = 0; it < 8; it++) {
        int i = tid + it * 256;
        int node = i >> 5, fq = (i & 31) << 2;
        float s = g_dinv[b * MESH + m0 + node];
        float4 v = *reinterpret_cast<const float4*>(Y + (size_t)node * DDIM + fq);
        smt[(fq + 0) * TSTR + node] = __float2half_rn(v.x * s);
        smt[(fq + 1) * TSTR + node] = __float2half_rn(v.y * s);
        smt[(fq + 2) * TSTR + node] = __float2half_rn(v.z * s);
        smt[(fq + 3) * TSTR + node] = __float2half_rn(v.w * s);
    }
    __syncthreads();
    __half* Ob = g_YsT + (size_t)b * DDIM * MESH + m0;
#pragma unroll
    for (int it = 0; it < 4; it++) {
        int i = tid + it * 256;
        int f = i >> 3, c = (i & 7) << 3;
        *reinterpret_cast<uint4*>(Ob + (size_t)f * MESH + c) =
            *reinterpret_cast<const uint4*>(&smt[f * TSTR + c]);
    }
}

// ---------------------------------------------------------------------------
// k_adj: S[b] = fp16(relu(E E^T)) -> gmem, dinv = rsqrt(1 + rowsum),
//        then (fused) layer-0 YsT = fp16(dinv * X) transposed.
// CTA 64 rows x 1024 cols, 8 warps (2 row-groups x 4 col-groups), tile 32x16.
// ---------------------------------------------------------------------------
__global__ __launch_bounds__(256, 3) void k_adj(const float* __restrict__ X) {
    __shared__ __align__(16) uint32_t Em[TM * SEW];
    __shared__ __align__(16) uint32_t En[2][TM * SEW];
    __shared__ float rsum[4][TM];
    __shared__ float dv[TM];

    const int b = blockIdx.y, m0 = blockIdx.x * TM;
    const int tid = threadIdx.x, w = tid >> 5, lane = tid & 31, g = lane >> 2, t = lane & 3;
    const int wr = w >> 2, wc = w & 3;
    const __half* Eb = g_Eh + (size_t)b * MESH * EDIM;

    const uint32_t aOff = (lane & 15) * 144 + (lane >> 4) * 16;
    const uint32_t bOff = ((lane & 7) + ((lane >> 4) << 3)) * 144 + ((lane >> 3) & 1) * 16;
    const uint32_t sEm = smem_u32(Em), sEn = smem_u32(En);

    for (int i = tid; i < 512; i += 256) {
        int r = i >> 3, c8 = i & 7;
        cpa16(&Em[r * SEW + c8 * 4], Eb + (m0 + r) * EDIM + c8 * 8);
    }
    auto loadEn = [&](int buf, int ch) {
        const __half* src = Eb + ch * KC * EDIM;
        uint32_t* dst = En[buf];
#pragma unroll
        for (int i = tid; i < 512; i += 256) {
            int r = i >> 3, c8 = i & 7;
            cpa16(&dst[r * SEW + c8 * 4], src + r * EDIM + c8 * 8);
        }
    };

    float rs0[2] = {0.f, 0.f}, rs1[2] = {0.f, 0.f};

    loadEn(0, 0); cpa_commit();
    for (int ch = 0; ch < NCH; ++ch) {
        if (ch + 1 < NCH) { loadEn((ch + 1) & 1, ch + 1); cpa_commit(); cpa_wait<1>(); }
        else cpa_wait<0>();
        __syncthreads();
        const uint32_t sEc = sEn + (ch & 1) * (TM * SEW * 4);

        float acc[2][2][4];
#pragma unroll
        for (int rb = 0; rb < 2; rb++)
#pragma unroll
            for (int j = 0; j < 2; j++)
                acc[rb][j][0] = acc[rb][j][1] = acc[rb][j][2] = acc[rb][j][3] = 0.f;

#pragma unroll
        for (int kk = 0; kk < 4; kk++) {
            uint32_t a[2][4], bb[4];
#pragma unroll
            for (int rb = 0; rb < 2; rb++)
                ldsm4(a[rb], sEm + aOff + (wr * 32 + rb * 16) * 144 + kk * 32);
            ldsm4(bb, sEc + bOff + (wc * 16) * 144 + kk * 32);
#pragma unroll
            for (int rb = 0; rb < 2; rb++) {
                mma16(acc[rb][0], a[rb], bb[0], bb[1]);
                mma16(acc[rb][1], a[rb], bb[2], bb[3]);
            }
        }

        __half* Sg = g_Sh + ((size_t)b * MESH + m0) * MESH + (size_t)ch * KC;
#pragma unroll
        for (int rb = 0; rb < 2; rb++) {
            const int row0 = wr * 32 + rb * 16 + g, row1 = row0 + 8;
#pragma unroll
            for (int j = 0; j < 2; j++) {
                const int col = wc * 16 + j * 8 + 2 * t;
                float v0 = fmaxf(acc[rb][j][0], 0.f), v1 = fmaxf(acc[rb][j][1], 0.f);
                float v2 = fmaxf(acc[rb][j][2], 0.f), v3 = fmaxf(acc[rb][j][3], 0.f);
                rs0[rb] += v0 + v1; rs1[rb] += v2 + v3;
                *reinterpret_cast<__half2*>(Sg + (size_t)row0 * MESH + col) =
                    __floats2half2_rn(v0, v1);
                *reinterpret_cast<__half2*>(Sg + (size_t)row1 * MESH + col) =
                    __floats2half2_rn(v2, v3);
            }
        }
        __syncthreads();
    }

#pragma unroll
    for (int rb = 0; rb < 2; rb++) {
        rs0[rb] += __shfl_xor_sync(0xffffffffu, rs0[rb], 1);
        rs0[rb] += __shfl_xor_sync(0xffffffffu, rs0[rb], 2);
        rs1[rb] += __shfl_xor_sync(0xffffffffu, rs1[rb], 1);
        rs1[rb] += __shfl_xor_sync(0xffffffffu, rs1[rb], 2);
    }
    if (t == 0) {
#pragma unroll
        for (int rb = 0; rb < 2; rb++) {
            rsum[wc][wr * 32 + rb * 16 + g]     = rs0[rb];
            rsum[wc][wr * 32 + rb * 16 + g + 8] = rs1[rb];
        }
    }
    __syncthreads();
    if (tid < TM) {
        float d = 1.f + rsum[0][tid] + rsum[1][tid] + rsum[2][tid] + rsum[3][tid];
        float r = rsqrtf(d);
        g_dinv[b * MESH + m0 + tid] = r;
        dv[tid] = r;
    }
    __syncthreads();

    // ---- fused layer-0 scale+transpose: YsT[b][f][m0+node] = fp16(dv[node]*X[node][f])
    __half* smt = reinterpret_cast<__half*>(Em);   // 128*TSTR halves = 18432 B, fits Em+En
    const float* Xb = X + ((size_t)b * MESH + m0) * DDIM;
#pragma unroll
    for (int it = 0; it < 8; it++) {
        int i = tid + it * 256;
        int node = i >> 5, fq = (i & 31) << 2;
        float s = dv[node];
        float4 v = *reinterpret_cast<const float4*>(Xb + (size_t)node * DDIM + fq);
        smt[(fq + 0) * TSTR + node] = __float2half_rn(v.x * s);
        smt[(fq + 1) * TSTR + node] = __float2half_rn(v.y * s);
        smt[(fq + 2) * TSTR + node] = __float2half_rn(v.z * s);
        smt[(fq + 3) * TSTR + node] = __float2half_rn(v.w * s);
    }
    __syncthreads();
    __half* Ob = g_YsT + (size_t)b * DDIM * MESH + m0;
#pragma unroll
    for (int it = 0; it < 4; it++) {
        int i = tid + it * 256;
        int f = i >> 3, c = (i & 7) << 3;
        *reinterpret_cast<uint4*>(Ob + (size_t)f * MESH + c) =
            *reinterpret_cast<const uint4*>(&smt[f * TSTR + c]);
    }
}

// ---------------------------------------------------------------------------
// k_gemm: Out = relu( [dinv_m*(S@Ys) + dinv_m^2*Y_m] @ W^T ).
// CTA 64x128, 256 threads, 8 warps (2 row-groups x 4 col-groups), tile 32x32.
// ---------------------------------------------------------------------------
#define GEMM_SMW (2 * TM * SEW + 2 * DDIM * SEW)  // 13824 words = 55296 B

__global__ __launch_bounds__(256, 3) void k_gemm(const float* __restrict__ Yraw,
                                                 const float* __restrict__ W,
                                                 float* __restrict__ Ob_base,
                                                 int layer) {
    extern __shared__ uint32_t smw[];
    uint32_t* Ss = smw;                    // [2][64][SEW]
    uint32_t* Xs = smw + 2 * TM * SEW;     // [2][128][SEW]
    uint32_t* T  = smw;                    // [64][STW]   (epilogue overlay)
    uint32_t* Wm = smw + TM * STW;         // [128][STW]  (epilogue overlay)

    const int b = blockIdx.y, m0 = blockIdx.x * TM;
    const int tid = threadIdx.x, w = tid >> 5, lane = tid & 31, g = lane >> 2, t = lane & 3;
    const int wr = w >> 2, wc = w & 3;
    const __half* Sb = g_Sh + ((size_t)b * MESH + m0) * MESH;
    const __half* Tb = g_YsT + (size_t)b * DDIM * MESH;
    const float* Yb = Yraw + (size_t)b * MESH * DDIM;
    float* Ob = Ob_base + (size_t)b * MESH * DDIM;

    const uint32_t aOff  = (lane & 15) * 144 + (lane >> 4) * 16;
    const uint32_t bOff  = ((lane & 7) + ((lane >> 4) << 3)) * 144 + ((lane >> 3) & 1) * 16;
    const uint32_t aOffE = (lane & 15) * 272 + (lane >> 4) * 16;
    const uint32_t bOffE = ((lane & 7) + ((lane >> 4) << 3)) * 272 + ((lane >> 3) & 1) * 16;
    const uint32_t sS0 = smem_u32(Ss), sX0 = smem_u32(Xs);
    const uint32_t sT = smem_u32(T), sW = smem_u32(Wm);

    auto loadSs = [&](int buf, int ch) {
        uint32_t* dst = Ss + buf * (TM * SEW);
#pragma unroll
        for (int i = tid; i < 512; i += 256) {
            int r = i >> 3, c8 = i & 7;
            cpa16(&dst[r * SEW + c8 * 4], Sb + (size_t)r * MESH + ch * KC + c8 * 8);
        }
    };
    auto loadXs = [&](int buf, int ch) {
        uint32_t* dst = Xs + buf * (DDIM * SEW);
#pragma unroll
        for (int i = tid; i < 1024; i += 256) {
            int r = i >> 3, c8 = i & 7;
            cpa16(&dst[r * SEW + c8 * 4], Tb + (size_t)r * MESH + ch * KC + c8 * 8);
        }
    };

    float p[2][4][4];
#pragma unroll
    for (int rb = 0; rb < 2; rb++)
#pragma unroll
        for (int j = 0; j < 4; j++)
            p[rb][j][0] = p[rb][j][1] = p[rb][j][2] = p[rb][j][3] = 0.f;

    loadSs(0, 0); loadXs(0, 0); cpa_commit();
    for (int ch = 0; ch < NCH; ++ch) {
        if (ch + 1 < NCH) {
            loadSs((ch + 1) & 1, ch + 1);
            loadXs((ch + 1) & 1, ch + 1);
            cpa_commit(); cpa_wait<1>();
        } else cpa_wait<0>();
        __syncthreads();
        const uint32_t sA = sS0 + (ch & 1) * (TM * SEW * 4);
        const uint32_t sB = sX0 + (ch & 1) * (DDIM * SEW * 4) + (wc * 32) * 144;

#pragma unroll
        for (int kk = 0; kk < 4; kk++) {
            uint32_t a[2][4], bb[2][4];
#pragma unroll
            for (int rb = 0; rb < 2; rb++)
                ldsm4(a[rb], sA + aOff + (wr * 32 + rb * 16) * 144 + kk * 32);
#pragma unroll
            for (int j2 = 0; j2 < 2; j2++)
                ldsm4(bb[j2], sB + bOff + j2 * 16 * 144 + kk * 32);
#pragma unroll
            for (int j2 = 0; j2 < 2; j2++)
#pragma unroll
                for (int rb = 0; rb < 2; rb++) {
                    mma16(p[rb][2 * j2],     a[rb], bb[j2][0], bb[j2][1]);
                    mma16(p[rb][2 * j2 + 1], a[rb], bb[j2][2], bb[j2][3]);
                }
        }
        __syncthreads();
    }

    // Epilogue: T = fp16(dm*P + dm^2*Y_m), then Out = relu(T @ W^T)
#pragma unroll
    for (int rb = 0; rb < 2; rb++) {
        const int row0 = wr * 32 + rb * 16 + g, row1 = row0 + 8;
        const float dm0 = g_dinv[b * MESH + m0 + row0];
        const float dm1 = g_dinv[b * MESH + m0 + row1];
#pragma unroll
        for (int j = 0; j < 4; j++) {
            const int col = wc * 32 + j * 8 + 2 * t;
            float2 y0 = *reinterpret_cast<const float2*>(Yb + (size_t)(m0 + row0) * DDIM + col);
            float2 y1 = *reinterpret_cast<const float2*>(Yb + (size_t)(m0 + row1) * DDIM + col);
            T[row0 * STW + wc * 16 + 4 * j + t] =
                h2u(__floats2half2_rn(dm0 * (p[rb][j][0] + dm0 * y0.x),
                                      dm0 * (p[rb][j][1] + dm0 * y0.y)));
            T[row1 * STW + wc * 16 + 4 * j + t] =
                h2u(__floats2half2_rn(dm1 * (p[rb][j][2] + dm1 * y1.x),
                                      dm1 * (p[rb][j][3] + dm1 * y1.y)));
        }
    }
    for (int i = tid; i < DDIM * 64; i += 256) {
        int r = i >> 6, c = i & 63;
        float2 wv = *reinterpret_cast<const float2*>(W + r * DDIM + 2 * c);
        Wm[r * STW + c] = h2u(__floats2half2_rn(wv.x, wv.y));
    }
    __syncthreads();

    float q[2][4][4];
#pragma unroll
    for (int rb = 0; rb < 2; rb++)
#pragma unroll
        for (int j = 0; j < 4; j++)
            q[rb][j][0] = q[rb][j][1] = q[rb][j][2] = q[rb][j][3] = 0.f;

#pragma unroll
    for (int kk = 0; kk < 8; kk++) {
        uint32_t a[2][4], bb[2][4];
#pragma unroll
        for (int rb = 0; rb < 2; rb++)
            ldsm4(a[rb], sT + aOffE + (wr * 32 + rb * 16) * 272 + kk * 32);
#pragma unroll
        for (int j2 = 0; j2 < 2; j2++)
            ldsm4(bb[j2], sW + bOffE + (wc * 32 + j2 * 16) * 272 + kk * 32);
#pragma unroll
        for (int j2 = 0; j2 < 2; j2++)
#pragma unroll
            for (int rb = 0; rb < 2; rb++) {
                mma16(q[rb][2 * j2],     a[rb], bb[j2][0], bb[j2][1]);
                mma16(q[rb][2 * j2 + 1], a[rb], bb[j2][2], bb[j2][3]);
            }
    }

#pragma unroll
    for (int rb = 0; rb < 2; rb++) {
        const int row0 = m0 + wr * 32 + rb * 16 + g, row1 = row0 + 8;
#pragma unroll
        for (int j = 0; j < 4; j++) {
            const int col = wc * 32 + j * 8 + 2 * t;
            *reinterpret_cast<float2*>(Ob + (size_t)row0 * DDIM + col) =
                make_float2(fmaxf(q[rb][j][0], 0.f), fmaxf(q[rb][j][1], 0.f));
            *reinterpret_cast<float2*>(Ob + (size_t)row1 * DDIM + col) =
                make_float2(fmaxf(q[rb][j][2], 0.f), fmaxf(q[rb][j][3], 0.f));
        }
    }
}

extern "C" void kernel_launch(void* const* d_in, const int* in_sizes, int n_in,
                              void* d_out, int out_size) {
    (void)in_sizes; (void)n_in; (void)out_size;
    const float* X  = (const float*)d_in[0];
    const float* E  = (const float*)d_in[1];
    const float* W1 = (const float*)d_in[2];
    const float* W2 = (const float*)d_in[3];
    float* out = (float*)d_out;

    cudaFuncSetAttribute(k_gemm, cudaFuncAttributeMaxDynamicSharedMemorySize,
                         GEMM_SMW * (int)sizeof(uint32_t));

    float* H1;
    cudaGetSymbolAddress((void**)&H1, g_H1);

    dim3 grid(MESH / TM, BATCH);
    dim3 sgrid(MESH / 64, BATCH);
    k_pre<<<BATCH * MESH * EDIM / 4 / 256, 256>>>(E);
    k_adj<<<grid, 256>>>(X);
    k_gemm<<<grid, 256, GEMM_SMW * sizeof(uint32_t)>>>(X, W1, H1, 0);
    k_scale<<<sgrid, 256>>>(1);
    k_gemm<<<grid, 256, GEMM_SMW * sizeof(uint32_t)>>>(H1, W2, out, 1);
}

// round 14
// speedup vs baseline: 2.3477x; 1.0536x over previous
#include <cuda_runtime.h>
#include <cuda_fp16.h>
#include <cstdint>

#define BATCH 32
#define MESH  1024
#define EDIM  64
#define DDIM  128
#define TM    64
#define KC    64
#define NCH   (MESH / KC)

#define SEW 36  // words per row, 64-half tiles (144 B): ldmatrix conflict-free
#define STW 68  // words per row, 128-half tiles (272 B): ldmatrix conflict-free
#define TSTR 72 // halves per feat row in transpose smem

__device__ float  g_dinv[BATCH * MESH];
__device__ __half g_Eh[BATCH * MESH * EDIM];
__device__ __half g_Sh[(size_t)BATCH * MESH * MESH];
__device__ __half g_YsT[(size_t)BATCH * DDIM * MESH];   // [b][feat][node]
__device__ float  g_H1[(size_t)BATCH * MESH * DDIM];

__device__ __forceinline__ uint32_t h2u(__half2 h) { return *reinterpret_cast<uint32_t*>(&h); }

// D(16x8,f32) += A(16x16,f16,row) * B(16x8,f16,col)
__device__ __forceinline__ void mma16(float* c, const uint32_t a[4], uint32_t b0, uint32_t b1) {
    asm volatile(
        "mma.sync.aligned.m16n8k16.row.col.f32.f16.f16.f32 "
        "{%0,%1,%2,%3}, {%4,%5,%6,%7}, {%8,%9}, {%0,%1,%2,%3};"
        : "+f"(c[0]), "+f"(c[1]), "+f"(c[2]), "+f"(c[3])
        : "r"(a[0]), "r"(a[1]), "r"(a[2]), "r"(a[3]), "r"(b0), "r"(b1));
}

__device__ __forceinline__ void ldsm4(uint32_t* r, uint32_t addr) {
    asm volatile("ldmatrix.sync.aligned.m8n8.x4.shared.b16 {%0,%1,%2,%3}, [%4];"
                 : "=r"(r[0]), "=r"(r[1]), "=r"(r[2]), "=r"(r[3]) : "r"(addr));
}

__device__ __forceinline__ uint32_t smem_u32(const void* p) {
    return (uint32_t)__cvta_generic_to_shared(p);
}
__device__ __forceinline__ void cpa16(void* dst, const void* src) {
    uint32_t d = (uint32_t)__cvta_generic_to_shared(dst);
    asm volatile("cp.async.cg.shared.global [%0], [%1], 16;" :: "r"(d), "l"(src));
}
__device__ __forceinline__ void cpa_commit() { asm volatile("cp.async.commit_group;"); }
template <int N>
__device__ __forceinline__ void cpa_wait() { asm volatile("cp.async.wait_group %0;" :: "n"(N)); }

// ---------------------------------------------------------------------------
// k_pre: E (f32) -> g_Eh (fp16)
// ---------------------------------------------------------------------------
__global__ __launch_bounds__(256) void k_pre(const float* __restrict__ E) {
    int i = blockIdx.x * 256 + threadIdx.x;
    float4 v = reinterpret_cast<const float4*>(E)[i];
    uint2 o;
    o.x = h2u(__floats2half2_rn(v.x, v.y));
    o.y = h2u(__floats2half2_rn(v.z, v.w));
    reinterpret_cast<uint2*>(g_Eh)[i] = o;
}

// ---------------------------------------------------------------------------
// k_adj: S[b] = fp16(relu(E E^T)) -> gmem, dinv = rsqrt(1 + rowsum),
//        then (fused) layer-0 YsT = fp16(dinv * X) transposed.
// ---------------------------------------------------------------------------
__global__ __launch_bounds__(256, 3) void k_adj(const float* __restrict__ X) {
    __shared__ __align__(16) uint32_t Em[TM * SEW];
    __shared__ __align__(16) uint32_t En[2][TM * SEW];
    __shared__ float rsum[4][TM];
    __shared__ float dv[TM];

    const int b = blockIdx.y, m0 = blockIdx.x * TM;
    const int tid = threadIdx.x, w = tid >> 5, lane = tid & 31, g = lane >> 2, t = lane & 3;
    const int wr = w >> 2, wc = w & 3;
    const __half* Eb = g_Eh + (size_t)b * MESH * EDIM;

    const uint32_t aOff = (lane & 15) * 144 + (lane >> 4) * 16;
    const uint32_t bOff = ((lane & 7) + ((lane >> 4) << 3)) * 144 + ((lane >> 3) & 1) * 16;
    const uint32_t sEm = smem_u32(Em), sEn = smem_u32(En);

    for (int i = tid; i < 512; i += 256) {
        int r = i >> 3, c8 = i & 7;
        cpa16(&Em[r * SEW + c8 * 4], Eb + (m0 + r) * EDIM + c8 * 8);
    }
    auto loadEn = [&](int buf, int ch) {
        const __half* src = Eb + ch * KC * EDIM;
        uint32_t* dst = En[buf];
#pragma unroll
        for (int i = tid; i < 512; i += 256) {
            int r = i >> 3, c8 = i & 7;
            cpa16(&dst[r * SEW + c8 * 4], src + r * EDIM + c8 * 8);
        }
    };

    float rs0[2] = {0.f, 0.f}, rs1[2] = {0.f, 0.f};

    loadEn(0, 0); cpa_commit();
    for (int ch = 0; ch < NCH; ++ch) {
        if (ch + 1 < NCH) { loadEn((ch + 1) & 1, ch + 1); cpa_commit(); cpa_wait<1>(); }
        else cpa_wait<0>();
        __syncthreads();
        const uint32_t sEc = sEn + (ch & 1) * (TM * SEW * 4);

        float acc[2][2][4];
#pragma unroll
        for (int rb = 0; rb < 2; rb++)
#pragma unroll
            for (int j = 0; j < 2; j++)
                acc[rb][j][0] = acc[rb][j][1] = acc[rb][j][2] = acc[rb][j][3] = 0.f;

#pragma unroll
        for (int kk = 0; kk < 4; kk++) {
            uint32_t a[2][4], bb[4];
#pragma unroll
            for (int rb = 0; rb < 2; rb++)
                ldsm4(a[rb], sEm + aOff + (wr * 32 + rb * 16) * 144 + kk * 32);
            ldsm4(bb, sEc + bOff + (wc * 16) * 144 + kk * 32);
#pragma unroll
            for (int rb = 0; rb < 2; rb++) {
                mma16(acc[rb][0], a[rb], bb[0], bb[1]);
                mma16(acc[rb][1], a[rb], bb[2], bb[3]);
            }
        }

        __half* Sg = g_Sh + ((size_t)b * MESH + m0) * MESH + (size_t)ch * KC;
#pragma unroll
        for (int rb = 0; rb < 2; rb++) {
            const int row0 = wr * 32 + rb * 16 + g, row1 = row0 + 8;
#pragma unroll
            for (int j = 0; j < 2; j++) {
                const int col = wc * 16 + j * 8 + 2 * t;
                float v0 = fmaxf(acc[rb][j][0], 0.f), v1 = fmaxf(acc[rb][j][1], 0.f);
                float v2 = fmaxf(acc[rb][j][2], 0.f), v3 = fmaxf(acc[rb][j][3], 0.f);
                rs0[rb] += v0 + v1; rs1[rb] += v2 + v3;
                *reinterpret_cast<__half2*>(Sg + (size_t)row0 * MESH + col) =
                    __floats2half2_rn(v0, v1);
                *reinterpret_cast<__half2*>(Sg + (size_t)row1 * MESH + col) =
                    __floats2half2_rn(v2, v3);
            }
        }
        __syncthreads();
    }

#pragma unroll
    for (int rb = 0; rb < 2; rb++) {
        rs0[rb] += __shfl_xor_sync(0xffffffffu, rs0[rb], 1);
        rs0[rb] += __shfl_xor_sync(0xffffffffu, rs0[rb], 2);
        rs1[rb] += __shfl_xor_sync(0xffffffffu, rs1[rb], 1);
        rs1[rb] += __shfl_xor_sync(0xffffffffu, rs1[rb], 2);
    }
    if (t == 0) {
#pragma unroll
        for (int rb = 0; rb < 2; rb++) {
            rsum[wc][wr * 32 + rb * 16 + g]     = rs0[rb];
            rsum[wc][wr * 32 + rb * 16 + g + 8] = rs1[rb];
        }
    }
    __syncthreads();
    if (tid < TM) {
        float d = 1.f + rsum[0][tid] + rsum[1][tid] + rsum[2][tid] + rsum[3][tid];
        float r = rsqrtf(d);
        g_dinv[b * MESH + m0 + tid] = r;
        dv[tid] = r;
    }
    __syncthreads();

    // fused layer-0 scale+transpose: YsT[b][f][m0+node] = fp16(dv[node]*X[node][f])
    __half* smt = reinterpret_cast<__half*>(Em);
    const float* Xb = X + ((size_t)b * MESH + m0) * DDIM;
#pragma unroll
    for (int it = 0; it < 8; it++) {
        int i = tid + it * 256;
        int node = i >> 5, fq = (i & 31) << 2;
        float s = dv[node];
        float4 v = *reinterpret_cast<const float4*>(Xb + (size_t)node * DDIM + fq);
        smt[(fq + 0) * TSTR + node] = __float2half_rn(v.x * s);
        smt[(fq + 1) * TSTR + node] = __float2half_rn(v.y * s);
        smt[(fq + 2) * TSTR + node] = __float2half_rn(v.z * s);
        smt[(fq + 3) * TSTR + node] = __float2half_rn(v.w * s);
    }
    __syncthreads();
    __half* Ob = g_YsT + (size_t)b * DDIM * MESH + m0;
#pragma unroll
    for (int it = 0; it < 4; it++) {
        int i = tid + it * 256;
        int f = i >> 3, c = (i & 7) << 3;
        *reinterpret_cast<uint4*>(Ob + (size_t)f * MESH + c) =
            *reinterpret_cast<const uint4*>(&smt[f * TSTR + c]);
    }
}

// ---------------------------------------------------------------------------
// k_gemm: Out = relu( [dinv_m*(S@Ys) + dinv_m^2*Y_m] @ W^T ).
// CTA 64x128, 8 warps (2x4), warp tile 32x32. 3-stage cp.async ring.
// layer 0 additionally emits g_YsT = fp16(dinv*Out) transposed.
// ---------------------------------------------------------------------------
#define STG_S (TM * SEW)            // 2304 words per S stage
#define STG_X (DDIM * SEW)          // 4608 words per X stage
#define GEMM_SMW (3 * (STG_S + STG_X))  // 20736 words = 82944 B

__global__ __launch_bounds__(256, 2) void k_gemm(const float* __restrict__ Yraw,
                                                 const float* __restrict__ W,
                                                 float* __restrict__ Ob_base,
                                                 int layer) {
    extern __shared__ uint32_t smw[];
    uint32_t* Ss = smw;                    // [3][64][SEW]
    uint32_t* Xs = smw + 3 * STG_S;        // [3][128][SEW]
    uint32_t* T  = smw;                    // [64][STW]   (epilogue overlay)
    uint32_t* Wm = smw + TM * STW;         // [128][STW]  (epilogue overlay)

    const int b = blockIdx.y, m0 = blockIdx.x * TM;
    const int tid = threadIdx.x, w = tid >> 5, lane = tid & 31, g = lane >> 2, t = lane & 3;
    const int wr = w >> 2, wc = w & 3;
    const __half* Sb = g_Sh + ((size_t)b * MESH + m0) * MESH;
    const __half* Tb = g_YsT + (size_t)b * DDIM * MESH;
    const float* Yb = Yraw + (size_t)b * MESH * DDIM;
    float* Ob = Ob_base + (size_t)b * MESH * DDIM;

    const uint32_t aOff  = (lane & 15) * 144 + (lane >> 4) * 16;
    const uint32_t bOff  = ((lane & 7) + ((lane >> 4) << 3)) * 144 + ((lane >> 3) & 1) * 16;
    const uint32_t aOffE = (lane & 15) * 272 + (lane >> 4) * 16;
    const uint32_t bOffE = ((lane & 7) + ((lane >> 4) << 3)) * 272 + ((lane >> 3) & 1) * 16;
    const uint32_t sS0 = smem_u32(Ss), sX0 = smem_u32(Xs);
    const uint32_t sT = smem_u32(T), sW = smem_u32(Wm);

    auto loadStage = [&](int slot, int ch) {
        uint32_t* dstS = Ss + slot * STG_S;
        uint32_t* dstX = Xs + slot * STG_X;
#pragma unroll
        for (int i = tid; i < 512; i += 256) {
            int r = i >> 3, c8 = i & 7;
            cpa16(&dstS[r * SEW + c8 * 4], Sb + (size_t)r * MESH + ch * KC + c8 * 8);
        }
#pragma unroll
        for (int i = tid; i < 1024; i += 256) {
            int r = i >> 3, c8 = i & 7;
            cpa16(&dstX[r * SEW + c8 * 4], Tb + (size_t)r * MESH + ch * KC + c8 * 8);
        }
        cpa_commit();
    };

    float p[2][4][4];
#pragma unroll
    for (int rb = 0; rb < 2; rb++)
#pragma unroll
        for (int j = 0; j < 4; j++)
            p[rb][j][0] = p[rb][j][1] = p[rb][j][2] = p[rb][j][3] = 0.f;

    loadStage(0, 0);
    loadStage(1, 1);
    for (int ch = 0; ch < NCH; ++ch) {
        if (ch == NCH - 1) cpa_wait<0>(); else cpa_wait<1>();
        __syncthreads();  // stage ch visible; compute(ch-1) done in all warps
        if (ch + 2 < NCH) loadStage((ch + 2) % 3, ch + 2);

        const int slot = ch % 3;
        const uint32_t sA = sS0 + slot * (STG_S * 4);
        const uint32_t sB = sX0 + slot * (STG_X * 4) + (wc * 32) * 144;

#pragma unroll
        for (int kk = 0; kk < 4; kk++) {
            uint32_t a[2][4], bb[2][4];
#pragma unroll
            for (int rb = 0; rb < 2; rb++)
                ldsm4(a[rb], sA + aOff + (wr * 32 + rb * 16) * 144 + kk * 32);
#pragma unroll
            for (int j2 = 0; j2 < 2; j2++)
                ldsm4(bb[j2], sB + bOff + j2 * 16 * 144 + kk * 32);
#pragma unroll
            for (int j2 = 0; j2 < 2; j2++)
#pragma unroll
                for (int rb = 0; rb < 2; rb++) {
                    mma16(p[rb][2 * j2],     a[rb], bb[j2][0], bb[j2][1]);
                    mma16(p[rb][2 * j2 + 1], a[rb], bb[j2][2], bb[j2][3]);
                }
        }
    }
    __syncthreads();  // mainloop smem reads done before epilogue overlay writes

    // Epilogue: T = fp16(dm*P + dm^2*Y_m), then Out = relu(T @ W^T)
#pragma unroll
    for (int rb = 0; rb < 2; rb++) {
        const int row0 = wr * 32 + rb * 16 + g, row1 = row0 + 8;
        const float dm0 = g_dinv[b * MESH + m0 + row0];
        const float dm1 = g_dinv[b * MESH + m0 + row1];
#pragma unroll
        for (int j = 0; j < 4; j++) {
            const int col = wc * 32 + j * 8 + 2 * t;
            float2 y0 = *reinterpret_cast<const float2*>(Yb + (size_t)(m0 + row0) * DDIM + col);
            float2 y1 = *reinterpret_cast<const float2*>(Yb + (size_t)(m0 + row1) * DDIM + col);
            T[row0 * STW + wc * 16 + 4 * j + t] =
                h2u(__floats2half2_rn(dm0 * (p[rb][j][0] + dm0 * y0.x),
                                      dm0 * (p[rb][j][1] + dm0 * y0.y)));
            T[row1 * STW + wc * 16 + 4 * j + t] =
                h2u(__floats2half2_rn(dm1 * (p[rb][j][2] + dm1 * y1.x),
                                      dm1 * (p[rb][j][3] + dm1 * y1.y)));
        }
    }
    for (int i = tid; i < DDIM * 64; i += 256) {
        int r = i >> 6, c = i & 63;
        float2 wv = *reinterpret_cast<const float2*>(W + r * DDIM + 2 * c);
        Wm[r * STW + c] = h2u(__floats2half2_rn(wv.x, wv.y));
    }
    __syncthreads();

    float q[2][4][4];
#pragma unroll
    for (int rb = 0; rb < 2; rb++)
#pragma unroll
        for (int j = 0; j < 4; j++)
            q[rb][j][0] = q[rb][j][1] = q[rb][j][2] = q[rb][j][3] = 0.f;

#pragma unroll
    for (int kk = 0; kk < 8; kk++) {
        uint32_t a[2][4], bb[2][4];
#pragma unroll
        for (int rb = 0; rb < 2; rb++)
            ldsm4(a[rb], sT + aOffE + (wr * 32 + rb * 16) * 272 + kk * 32);
#pragma unroll
        for (int j2 = 0; j2 < 2; j2++)
            ldsm4(bb[j2], sW + bOffE + (wc * 32 + j2 * 16) * 272 + kk * 32);
#pragma unroll
        for (int j2 = 0; j2 < 2; j2++)
#pragma unroll
            for (int rb = 0; rb < 2; rb++) {
                mma16(q[rb][2 * j2],     a[rb], bb[j2][0], bb[j2][1]);
                mma16(q[rb][2 * j2 + 1], a[rb], bb[j2][2], bb[j2][3]);
            }
    }

    // relu + store output (f32)
#pragma unroll
    for (int rb = 0; rb < 2; rb++) {
        const int row0 = m0 + wr * 32 + rb * 16 + g, row1 = row0 + 8;
#pragma unroll
        for (int j = 0; j < 4; j++) {
            const int col = wc * 32 + j * 8 + 2 * t;
            q[rb][j][0] = fmaxf(q[rb][j][0], 0.f); q[rb][j][1] = fmaxf(q[rb][j][1], 0.f);
            q[rb][j][2] = fmaxf(q[rb][j][2], 0.f); q[rb][j][3] = fmaxf(q[rb][j][3], 0.f);
            *reinterpret_cast<float2*>(Ob + (size_t)row0 * DDIM + col) =
                make_float2(q[rb][j][0], q[rb][j][1]);
            *reinterpret_cast<float2*>(Ob + (size_t)row1 * DDIM + col) =
                make_float2(q[rb][j][2], q[rb][j][3]);
        }
    }

    // layer 0 only: emit g_YsT tile = fp16(dinv_row * Out) transposed
    if (layer == 0) {
        __syncthreads();  // done reading T/Wm overlays
        __half* smt = reinterpret_cast<__half*>(smw);  // 128*TSTR halves = 4608 words
#pragma unroll
        for (int rb = 0; rb < 2; rb++) {
            const int row0 = wr * 32 + rb * 16 + g, row1 = row0 + 8;
            const float dm0 = g_dinv[b * MESH + m0 + row0];
            const float dm1 = g_dinv[b * MESH + m0 + row1];
#pragma unroll
            for (int j = 0; j < 4; j++) {
                const int col = wc * 32 + j * 8 + 2 * t;
                smt[(col + 0) * TSTR + row0] = __float2half_rn(q[rb][j][0] * dm0);
                smt[(col + 1) * TSTR + row0] = __float2half_rn(q[rb][j][1] * dm0);
                smt[(col + 0) * TSTR + row1] = __float2half_rn(q[rb][j][2] * dm1);
                smt[(col + 1) * TSTR + row1] = __float2half_rn(q[rb][j][3] * dm1);
            }
        }
        __syncthreads();
        __half* Oy = g_YsT + (size_t)b * DDIM * MESH + m0;
#pragma unroll
        for (int it = 0; it < 4; it++) {
            int i = tid + it * 256;
            int f = i >> 3, c = (i & 7) << 3;
            *reinterpret_cast<uint4*>(Oy + (size_t)f * MESH + c) =
                *reinterpret_cast<const uint4*>(&smt[f * TSTR + c]);
        }
    }
}

extern "C" void kernel_launch(void* const* d_in, const int* in_sizes, int n_in,
                              void* d_out, int out_size) {
    (void)in_sizes; (void)n_in; (void)out_size;
    const float* X  = (const float*)d_in[0];
    const float* E  = (const float*)d_in[1];
    const float* W1 = (const float*)d_in[2];
    const float* W2 = (const float*)d_in[3];
    float* out = (float*)d_out;

    cudaFuncSetAttribute(k_gemm, cudaFuncAttributeMaxDynamicSharedMemorySize,
                         GEMM_SMW * (int)sizeof(uint32_t));

    float* H1;
    cudaGetSymbolAddress((void**)&H1, g_H1);

    dim3 grid(MESH / TM, BATCH);
    k_pre<<<BATCH * MESH * EDIM / 4 / 256, 256>>>(E);
    k_adj<<<grid, 256>>>(X);
    k_gemm<<<grid, 256, GEMM_SMW * sizeof(uint32_t)>>>(X, W1, H1, 0);
    k_gemm<<<grid, 256, GEMM_SMW * sizeof(uint32_t)>>>(H1, W2, out, 1);
}